// round 1
// baseline (speedup 1.0000x reference)
#include <cuda_runtime.h>
#include <cstdint>
#include <cstddef>

// Problem constants (fixed shapes: x[8,256,128,128], params[8,512], W[256,512])
#define B_   8
#define C_   256
#define HW_  16384
#define EPS_ 1e-5f

// ---------------------------------------------------------------------------
// Device scratch (no allocations allowed anywhere)
// ---------------------------------------------------------------------------
__device__ float2 g_sums[B_ * C_];          // per (b,c): {sum, sumsq}
__device__ float  g_meanI[B_ * C_];
__device__ float  g_rI[B_ * C_];
__device__ float  g_mlrl[B_ * 2];           // per b: {LN mean, LN rstd}
__device__ float  g_Aeff[(size_t)B_ * C_ * C_];  // [b][i(k)][o(m)]  k-major!
__device__ float  g_bias[B_ * C_];

// ---------------------------------------------------------------------------
// Helpers
// ---------------------------------------------------------------------------
__device__ __forceinline__ float warp_sum(float v) {
#pragma unroll
    for (int o = 16; o > 0; o >>= 1) v += __shfl_xor_sync(0xffffffffu, v, o);
    return v;
}

__device__ __forceinline__ unsigned long long ffma2(unsigned long long a,
                                                    unsigned long long b,
                                                    unsigned long long c) {
    unsigned long long d;
    asm("fma.rn.f32x2 %0, %1, %2, %3;" : "=l"(d) : "l"(a), "l"(b), "l"(c));
    return d;
}

__device__ __forceinline__ unsigned long long pack2(float lo, float hi) {
    unsigned long long d;
    asm("mov.b64 %0, {%1, %2};" : "=l"(d) : "f"(lo), "f"(hi));
    return d;
}

__device__ __forceinline__ float2 unpack2(unsigned long long v) {
    float2 r;
    asm("mov.b64 {%0, %1}, %2;" : "=f"(r.x), "=f"(r.y) : "l"(v));
    return r;
}

// ---------------------------------------------------------------------------
// Kernel 1: per-(b,c) sum / sumsq over 16384 pixels. 1 block per (b,c).
// ---------------------------------------------------------------------------
__global__ void stats_k(const float* __restrict__ x) {
    int bc = blockIdx.x;
    const float4* xp = (const float4*)(x + (size_t)bc * HW_);
    float s = 0.f, s2 = 0.f;
#pragma unroll
    for (int it = 0; it < 16; ++it) {
        float4 v = xp[threadIdx.x + it * 256];
        s  += v.x + v.y + v.z + v.w;
        s2 += v.x * v.x + v.y * v.y + v.z * v.z + v.w * v.w;
    }
    s = warp_sum(s);
    s2 = warp_sum(s2);
    __shared__ float sh[2][8];
    int w = threadIdx.x >> 5, l = threadIdx.x & 31;
    if (l == 0) { sh[0][w] = s; sh[1][w] = s2; }
    __syncthreads();
    if (threadIdx.x == 0) {
        float S = 0.f, S2 = 0.f;
#pragma unroll
        for (int i = 0; i < 8; ++i) { S += sh[0][i]; S2 += sh[1][i]; }
        g_sums[bc] = make_float2(S, S2);
    }
}

// ---------------------------------------------------------------------------
// Kernel 2: finalize IN stats per (b,c); aggregate LN stats per b.
// 1 block per batch, thread = channel.
// ---------------------------------------------------------------------------
__global__ void finalize_k() {
    int b = blockIdx.x, c = threadIdx.x;
    float2 sv = g_sums[b * C_ + c];
    const float inv = 1.0f / (float)HW_;
    float m = sv.x * inv;
    float v = fmaxf(sv.y * inv - m * m, 0.f);
    g_meanI[b * C_ + c] = m;
    g_rI[b * C_ + c]    = rsqrtf(v + EPS_);

    float s  = warp_sum(sv.x);
    float s2 = warp_sum(sv.y);
    __shared__ float sh[2][8];
    int w = c >> 5, l = c & 31;
    if (l == 0) { sh[0][w] = s; sh[1][w] = s2; }
    __syncthreads();
    if (c == 0) {
        float S = 0.f, S2 = 0.f;
#pragma unroll
        for (int i = 0; i < 8; ++i) { S += sh[0][i]; S2 += sh[1][i]; }
        const float invN = 1.0f / ((float)C_ * (float)HW_);
        float M = S * invN;
        float V = fmaxf(S2 * invN - M * M, 0.f);
        g_mlrl[b * 2]     = M;
        g_mlrl[b * 2 + 1] = rsqrtf(V + EPS_);
    }
}

// ---------------------------------------------------------------------------
// Kernel 3: build effective weights + bias.
//   Aeff[b][i][o] = gamma[b,o] * (W1[o,i]*rI[b,i] + W2[o,i]*rL[b])   (k-major)
//   bias[b][o]    = beta[b,o] - gamma[b,o] * sum_i (W1*rI*muI + W2*rL*muL)
// 1 block per (b,o), thread = i.
// ---------------------------------------------------------------------------
__global__ void prep_k(const float* __restrict__ W,
                       const float* __restrict__ params) {
    int b = blockIdx.x >> 8;
    int o = blockIdx.x & 255;
    int i = threadIdx.x;

    float w1 = W[o * (2 * C_) + i];
    float w2 = W[o * (2 * C_) + C_ + i];
    float ri = g_rI[b * C_ + i];
    float mi = g_meanI[b * C_ + i];
    float ml = g_mlrl[b * 2];
    float rl = g_mlrl[b * 2 + 1];
    float gamma = params[b * (2 * C_) + o];
    float beta  = params[b * (2 * C_) + C_ + o];

    g_Aeff[((size_t)(b * C_ + i)) * C_ + o] = gamma * (w1 * ri + w2 * rl);

    float p = w1 * ri * mi + w2 * rl * ml;
    p = warp_sum(p);
    __shared__ float sh[8];
    int w = i >> 5, l = i & 31;
    if (l == 0) sh[w] = p;
    __syncthreads();
    if (i == 0) {
        float P = 0.f;
#pragma unroll
        for (int j = 0; j < 8; ++j) P += sh[j];
        g_bias[b * C_ + o] = beta - gamma * P;
    }
}

// ---------------------------------------------------------------------------
// Kernel 4: per-batch GEMM  out[b][m][n] = sum_k Aeff[b][k][m] * x[b][k][n] + bias
// 128x128 CTA tile, BK=16, double-buffered SMEM, packed f32x2 FMA inner loop.
// ---------------------------------------------------------------------------
__global__ __launch_bounds__(256, 2)
void gemm_k(const float* __restrict__ x, float* __restrict__ out) {
    constexpr int BK = 16;
    __shared__ float As[2][BK][128];
    __shared__ float Bs[2][BK][128];

    int b  = blockIdx.z;
    int m0 = blockIdx.y << 7;
    int n0 = blockIdx.x << 7;
    int tid = threadIdx.x;
    int tx = tid & 15, ty = tid >> 4;

    const float* Ab = g_Aeff + (size_t)b * (C_ * C_);       // [k][m], k-major
    const float* Xb = x + (size_t)b * C_ * HW_;             // [k][n]

    int ka0 = tid >> 5;            // 0..7
    int ma0 = (tid & 31) << 2;     // 0,4,...,124
    int ka1 = ka0 + 8;

    unsigned long long acc[8][4];
#pragma unroll
    for (int i = 0; i < 8; ++i)
#pragma unroll
        for (int j = 0; j < 4; ++j) acc[i][j] = 0ull;

    // prologue: tile 0 -> buf 0
    float4 pa0 = *(const float4*)(Ab + ka0 * C_ + m0 + ma0);
    float4 pa1 = *(const float4*)(Ab + ka1 * C_ + m0 + ma0);
    float4 pb0 = *(const float4*)(Xb + (size_t)ka0 * HW_ + n0 + ma0);
    float4 pb1 = *(const float4*)(Xb + (size_t)ka1 * HW_ + n0 + ma0);
    *(float4*)&As[0][ka0][ma0] = pa0;
    *(float4*)&As[0][ka1][ma0] = pa1;
    *(float4*)&Bs[0][ka0][ma0] = pb0;
    *(float4*)&Bs[0][ka1][ma0] = pb1;
    __syncthreads();

    int buf = 0;
    const int NK = C_ / BK;   // 16
    for (int kt = 0; kt < NK; ++kt) {
        int k0n = (kt + 1) * BK;
        if (kt + 1 < NK) {   // prefetch next tile into registers (hides LDG latency)
            pa0 = *(const float4*)(Ab + (k0n + ka0) * C_ + m0 + ma0);
            pa1 = *(const float4*)(Ab + (k0n + ka1) * C_ + m0 + ma0);
            pb0 = *(const float4*)(Xb + (size_t)(k0n + ka0) * HW_ + n0 + ma0);
            pb1 = *(const float4*)(Xb + (size_t)(k0n + ka1) * HW_ + n0 + ma0);
        }
#pragma unroll
        for (int k = 0; k < BK; ++k) {
            const float* ap = &As[buf][k][ty << 3];
            float4 a0 = *(const float4*)ap;
            float4 a1 = *(const float4*)(ap + 4);
            const ulonglong2* bp = (const ulonglong2*)&Bs[buf][k][tx << 3];
            ulonglong2 q0 = bp[0];
            ulonglong2 q1 = bp[1];
            unsigned long long bv0 = q0.x, bv1 = q0.y, bv2 = q1.x, bv3 = q1.y;
            float av[8] = {a0.x, a0.y, a0.z, a0.w, a1.x, a1.y, a1.z, a1.w};
#pragma unroll
            for (int i = 0; i < 8; ++i) {
                unsigned long long ad = pack2(av[i], av[i]);
                acc[i][0] = ffma2(ad, bv0, acc[i][0]);
                acc[i][1] = ffma2(ad, bv1, acc[i][1]);
                acc[i][2] = ffma2(ad, bv2, acc[i][2]);
                acc[i][3] = ffma2(ad, bv3, acc[i][3]);
            }
        }
        if (kt + 1 < NK) {
            *(float4*)&As[buf ^ 1][ka0][ma0] = pa0;
            *(float4*)&As[buf ^ 1][ka1][ma0] = pa1;
            *(float4*)&Bs[buf ^ 1][ka0][ma0] = pb0;
            *(float4*)&Bs[buf ^ 1][ka1][ma0] = pb1;
        }
        __syncthreads();
        buf ^= 1;
    }

    // epilogue: add bias, store
#pragma unroll
    for (int i = 0; i < 8; ++i) {
        int m = m0 + (ty << 3) + i;
        float bb = g_bias[b * C_ + m];
        float* op = out + (size_t)(b * C_ + m) * HW_ + n0 + (tx << 3);
        float2 r0 = unpack2(acc[i][0]);
        float2 r1 = unpack2(acc[i][1]);
        float2 r2 = unpack2(acc[i][2]);
        float2 r3 = unpack2(acc[i][3]);
        *(float4*)op       = make_float4(r0.x + bb, r0.y + bb, r1.x + bb, r1.y + bb);
        *(float4*)(op + 4) = make_float4(r2.x + bb, r2.y + bb, r3.x + bb, r3.y + bb);
    }
}

// ---------------------------------------------------------------------------
// Launch
// ---------------------------------------------------------------------------
extern "C" void kernel_launch(void* const* d_in, const int* in_sizes, int n_in,
                              void* d_out, int out_size) {
    const float* x      = (const float*)d_in[0];   // [8,256,128,128]
    const float* params = (const float*)d_in[1];   // [8,512]
    const float* W      = (const float*)d_in[2];   // [256,512]
    float* out = (float*)d_out;

    stats_k<<<B_ * C_, 256>>>(x);
    finalize_k<<<B_, 256>>>();
    prep_k<<<B_ * C_, 256>>>(W, params);

    dim3 grid(HW_ / 128, C_ / 128, B_);
    gemm_k<<<grid, 256>>>(x, out);
}

// round 4
// speedup vs baseline: 1.3639x; 1.3639x over previous
#include <cuda_runtime.h>
#include <cuda_bf16.h>
#include <cstdint>
#include <cstddef>

#define B_   8
#define C_   256
#define HW_  16384
#define EPS_ 1e-5f

// ---------------------------------------------------------------------------
// Device scratch
// ---------------------------------------------------------------------------
__device__ float2 g_sums[B_ * C_];
__device__ float  g_meanI[B_ * C_];
__device__ float  g_rI[B_ * C_];
__device__ float  g_mlrl[B_ * 2];
__device__ float  g_bias[B_ * C_];
// Aeff split to bf16 hi/lo, k-major [b][m(o)][k(i)]
__device__ __align__(16) __nv_bfloat16 g_Ah[(size_t)B_ * 65536];
__device__ __align__(16) __nv_bfloat16 g_Al[(size_t)B_ * 65536];

// ---------------------------------------------------------------------------
// Helpers
// ---------------------------------------------------------------------------
__device__ __forceinline__ float warp_sum(float v) {
#pragma unroll
    for (int o = 16; o > 0; o >>= 1) v += __shfl_xor_sync(0xffffffffu, v, o);
    return v;
}
// pack: 'first' -> low 16 bits, 'second' -> high 16 bits
__device__ __forceinline__ uint32_t pack_bf16x2(float first, float second) {
    uint32_t r;
    asm("cvt.rn.bf16x2.f32 %0, %1, %2;" : "=r"(r) : "f"(second), "f"(first));
    return r;
}
__device__ __forceinline__ void mma_bf16(float* d, const uint32_t* a, const uint32_t* b) {
    asm volatile(
        "mma.sync.aligned.m16n8k16.row.col.f32.bf16.bf16.f32 "
        "{%0,%1,%2,%3}, {%4,%5,%6,%7}, {%8,%9}, {%0,%1,%2,%3};"
        : "+f"(d[0]), "+f"(d[1]), "+f"(d[2]), "+f"(d[3])
        : "r"(a[0]), "r"(a[1]), "r"(a[2]), "r"(a[3]), "r"(b[0]), "r"(b[1]));
}

// ---------------------------------------------------------------------------
// Kernel 1: per-(b,c) sum / sumsq over 16384 pixels. 1 block per (b,c).
// ---------------------------------------------------------------------------
__global__ void stats_k(const float* __restrict__ x) {
    int bc = blockIdx.x;
    const float4* xp = (const float4*)(x + (size_t)bc * HW_);
    float s = 0.f, s2 = 0.f;
#pragma unroll
    for (int it = 0; it < 16; ++it) {
        float4 v = xp[threadIdx.x + it * 256];
        s  += v.x + v.y + v.z + v.w;
        s2 += v.x * v.x + v.y * v.y + v.z * v.z + v.w * v.w;
    }
    s = warp_sum(s); s2 = warp_sum(s2);
    __shared__ float sh[2][8];
    int w = threadIdx.x >> 5, l = threadIdx.x & 31;
    if (l == 0) { sh[0][w] = s; sh[1][w] = s2; }
    __syncthreads();
    if (threadIdx.x == 0) {
        float S = 0.f, S2 = 0.f;
#pragma unroll
        for (int i = 0; i < 8; ++i) { S += sh[0][i]; S2 += sh[1][i]; }
        g_sums[bc] = make_float2(S, S2);
    }
}

// ---------------------------------------------------------------------------
// Kernel 2: finalize IN / LN stats
// ---------------------------------------------------------------------------
__global__ void finalize_k() {
    int b = blockIdx.x, c = threadIdx.x;
    float2 sv = g_sums[b * C_ + c];
    const float inv = 1.0f / (float)HW_;
    float m = sv.x * inv;
    float v = fmaxf(sv.y * inv - m * m, 0.f);
    g_meanI[b * C_ + c] = m;
    g_rI[b * C_ + c]    = rsqrtf(v + EPS_);
    float s = warp_sum(sv.x), s2 = warp_sum(sv.y);
    __shared__ float sh[2][8];
    int w = c >> 5, l = c & 31;
    if (l == 0) { sh[0][w] = s; sh[1][w] = s2; }
    __syncthreads();
    if (c == 0) {
        float S = 0.f, S2 = 0.f;
#pragma unroll
        for (int i = 0; i < 8; ++i) { S += sh[0][i]; S2 += sh[1][i]; }
        const float invN = 1.0f / ((float)C_ * (float)HW_);
        float M = S * invN;
        float V = fmaxf(S2 * invN - M * M, 0.f);
        g_mlrl[b * 2]     = M;
        g_mlrl[b * 2 + 1] = rsqrtf(V + EPS_);
    }
}

// ---------------------------------------------------------------------------
// Kernel 3: build Aeff bf16 hi/lo + bias.  block=(b,o), thread=i(k)
// ---------------------------------------------------------------------------
__global__ void prep_k(const float* __restrict__ W,
                       const float* __restrict__ params) {
    int b = blockIdx.x >> 8;
    int o = blockIdx.x & 255;
    int i = threadIdx.x;

    float w1 = W[o * (2 * C_) + i];
    float w2 = W[o * (2 * C_) + C_ + i];
    float ri = g_rI[b * C_ + i];
    float mi = g_meanI[b * C_ + i];
    float ml = g_mlrl[b * 2];
    float rl = g_mlrl[b * 2 + 1];
    float gamma = params[b * (2 * C_) + o];
    float beta  = params[b * (2 * C_) + C_ + o];

    float a = gamma * (w1 * ri + w2 * rl);
    __nv_bfloat16 h = __float2bfloat16(a);
    float lo = a - __bfloat162float(h);
    size_t idx = (size_t)b * 65536 + o * 256 + i;
    g_Ah[idx] = h;
    g_Al[idx] = __float2bfloat16(lo);

    float p = w1 * ri * mi + w2 * rl * ml;
    p = warp_sum(p);
    __shared__ float sh[8];
    int w = i >> 5, l = i & 31;
    if (l == 0) sh[w] = p;
    __syncthreads();
    if (i == 0) {
        float P = 0.f;
#pragma unroll
        for (int j = 0; j < 8; ++j) P += sh[j];
        g_bias[b * C_ + o] = beta - gamma * P;
    }
}

// ---------------------------------------------------------------------------
// Kernel 4: mma.sync bf16 GEMM.
//   out[b][m][n] = sum_k Aeff[b][m][k] * x[b][k][n] + bias[b][m]
//   CTA: full M=256, N-tile=128 pixels, K=256 (4 chunks of 64).
//   3-term split: Ah*xh + Al*xh + Ah*xl  (drops lo*lo ~ 2^-16 rel).
// SMEM word layout (uint32 units):
//   xh [128 n][132]   @ 0        (k-pair words; stride 132 -> conflict-free)
//   xl [128 n][132]   @ 16896
//   Ah [256 m][36]    @ 33792    (64-k chunk = 32 words + pad)
//   Al [256 m][36]    @ 43008
//   bias[256]         @ 52224
// ---------------------------------------------------------------------------
#define SX 132
#define SA 36
#define OFF_XH   0
#define OFF_XL   16896
#define OFF_AH   33792
#define OFF_AL   43008
#define OFF_BIAS 52224
#define SMEM_WORDS 52480
#define SMEM_BYTES (SMEM_WORDS * 4)

__global__ __launch_bounds__(256, 1)
void gemm_tc(const float* __restrict__ x, float* __restrict__ out) {
    extern __shared__ uint32_t sm[];
    uint32_t* s_xh = sm + OFF_XH;
    uint32_t* s_xl = sm + OFF_XL;
    uint32_t* s_Ah = sm + OFF_AH;
    uint32_t* s_Al = sm + OFF_AL;
    float*    s_bias = (float*)(sm + OFF_BIAS);

    int t = threadIdx.x;
    int b = blockIdx.y;
    int n0 = blockIdx.x << 7;
    int lane = t & 31, wid = t >> 5;

    s_bias[t] = g_bias[b * C_ + t];

    // ---- Phase 1: convert x tile [256 k][128 n] -> bf16 hi/lo, smem [n][kw] ----
    {
        int nl = lane >> 2, kwl = lane & 3;
        const float* xb = x + (size_t)b * C_ * HW_ + n0;
#pragma unroll 4
        for (int it = 0; it < 64; ++it) {
            int bid = wid + (it << 3);            // 0..511
            int n  = ((bid & 15) << 3) + nl;      // 0..127
            int kw = ((bid >> 4) << 2) + kwl;     // 0..127
            int k  = kw << 1;
            float f0 = xb[(size_t)k * HW_ + n];
            float f1 = xb[(size_t)(k + 1) * HW_ + n];
            float g0 = f0 - __bfloat162float(__float2bfloat16(f0));
            float g1 = f1 - __bfloat162float(__float2bfloat16(f1));
            s_xh[n * SX + kw] = pack_bf16x2(f0, f1);
            s_xl[n * SX + kw] = pack_bf16x2(g0, g1);
        }
    }
    __syncthreads();

    // ---- Phase 2: K-chunked mma mainloop ----
    const __nv_bfloat16* gAh = g_Ah + (size_t)b * 65536;
    const __nv_bfloat16* gAl = g_Al + (size_t)b * 65536;
    int wm = wid >> 1;              // 0..3  -> 64 m rows
    int wn = wid & 1;               // 0..1  -> 64 n cols
    int gq = lane >> 2;             // group id 0..7
    int tg = lane & 3;              // thread-in-group 0..3

    float acc[4][8][4];
#pragma unroll
    for (int i = 0; i < 4; ++i)
#pragma unroll
        for (int j = 0; j < 8; ++j)
#pragma unroll
            for (int q = 0; q < 4; ++q) acc[i][j][q] = 0.f;

    int ccol = t & 7;               // 16B column 0..7 within 128B chunk row
    int crow = t >> 3;              // 0..31

    for (int c = 0; c < 4; ++c) {
        // copy A 64-k chunk (hi+lo) into padded smem
#pragma unroll
        for (int rb = 0; rb < 8; ++rb) {
            int m = rb * 32 + crow;
            size_t goff = (size_t)m * 256 + c * 64;
            uint4 vh = *(const uint4*)((const char*)(gAh + goff) + ccol * 16);
            uint4 vl = *(const uint4*)((const char*)(gAl + goff) + ccol * 16);
            *(uint4*)&s_Ah[m * SA + ccol * 4] = vh;
            *(uint4*)&s_Al[m * SA + ccol * 4] = vl;
        }
        __syncthreads();

#pragma unroll
        for (int ks = 0; ks < 4; ++ks) {
            int kwx = c * 32 + ks * 8;
            int kwa = ks * 8;

            uint32_t bh[8][2];
#pragma unroll
            for (int nt = 0; nt < 8; ++nt) {
                int n = wn * 64 + nt * 8 + gq;
                int w = n * SX + kwx + tg;
                bh[nt][0] = s_xh[w];
                bh[nt][1] = s_xh[w + 4];
            }
            uint32_t ah[4][4];
#pragma unroll
            for (int mt = 0; mt < 4; ++mt) {
                int m = wm * 64 + mt * 16 + gq;
                int w = m * SA + kwa + tg;
                ah[mt][0] = s_Ah[w];
                ah[mt][1] = s_Ah[w + 8 * SA];
                ah[mt][2] = s_Ah[w + 4];
                ah[mt][3] = s_Ah[w + 8 * SA + 4];
            }
            // term 1: Ah * xh
#pragma unroll
            for (int mt = 0; mt < 4; ++mt)
#pragma unroll
                for (int nt = 0; nt < 8; ++nt)
                    mma_bf16(acc[mt][nt], ah[mt], bh[nt]);

            // term 2: Al * xh
            uint32_t al[4][4];
#pragma unroll
            for (int mt = 0; mt < 4; ++mt) {
                int m = wm * 64 + mt * 16 + gq;
                int w = m * SA + kwa + tg;
                al[mt][0] = s_Al[w];
                al[mt][1] = s_Al[w + 8 * SA];
                al[mt][2] = s_Al[w + 4];
                al[mt][3] = s_Al[w + 8 * SA + 4];
            }
#pragma unroll
            for (int mt = 0; mt < 4; ++mt)
#pragma unroll
                for (int nt = 0; nt < 8; ++nt)
                    mma_bf16(acc[mt][nt], al[mt], bh[nt]);

            // term 3: Ah * xl  (reuse bh regs)
#pragma unroll
            for (int nt = 0; nt < 8; ++nt) {
                int n = wn * 64 + nt * 8 + gq;
                int w = n * SX + kwx + tg;
                bh[nt][0] = s_xl[w];
                bh[nt][1] = s_xl[w + 4];
            }
#pragma unroll
            for (int mt = 0; mt < 4; ++mt)
#pragma unroll
                for (int nt = 0; nt < 8; ++nt)
                    mma_bf16(acc[mt][nt], ah[mt], bh[nt]);
        }
        __syncthreads();
    }

    // ---- Phase 3: epilogue ----
#pragma unroll
    for (int mt = 0; mt < 4; ++mt) {
        int m = wm * 64 + mt * 16 + gq;
        float b0 = s_bias[m];
        float b1 = s_bias[m + 8];
#pragma unroll
        for (int nt = 0; nt < 8; ++nt) {
            int n = n0 + wn * 64 + nt * 8 + tg * 2;
            float* o0 = out + ((size_t)(b * C_ + m)) * HW_ + n;
            float2 v0 = make_float2(acc[mt][nt][0] + b0, acc[mt][nt][1] + b0);
            float2 v1 = make_float2(acc[mt][nt][2] + b1, acc[mt][nt][3] + b1);
            *(float2*)o0 = v0;
            *(float2*)(o0 + (size_t)8 * HW_) = v1;
        }
    }
}

// ---------------------------------------------------------------------------
// Launch
// ---------------------------------------------------------------------------
extern "C" void kernel_launch(void* const* d_in, const int* in_sizes, int n_in,
                              void* d_out, int out_size) {
    const float* x      = (const float*)d_in[0];
    const float* params = (const float*)d_in[1];
    const float* W      = (const float*)d_in[2];
    float* out = (float*)d_out;

    // Idempotent, capture-safe; no static state (harness rules).
    cudaFuncSetAttribute(gemm_tc, cudaFuncAttributeMaxDynamicSharedMemorySize,
                         SMEM_BYTES);

    stats_k<<<B_ * C_, 256>>>(x);
    finalize_k<<<B_, 256>>>();
    prep_k<<<B_ * C_, 256>>>(W, params);
    dim3 grid(HW_ / 128, B_);
    gemm_tc<<<grid, 256, SMEM_BYTES>>>(x, out);
}

// round 5
// speedup vs baseline: 1.6156x; 1.1846x over previous
#include <cuda_runtime.h>
#include <cuda_bf16.h>
#include <cstdint>
#include <cstddef>

#define B_   8
#define C_   256
#define HW_  16384
#define EPS_ 1e-5f

// ---------------------------------------------------------------------------
// Device scratch
// ---------------------------------------------------------------------------
__device__ float2 g_sums[B_ * C_];
__device__ float  g_meanI[B_ * C_];
__device__ float  g_rI[B_ * C_];
__device__ float  g_mlrl[B_ * 2];
__device__ float  g_bias[B_ * C_];
// Aeff bf16 hi/lo in padded per-chunk layout for linear cp.async:
//   [b][chunk(8)][m(256)][40 bf16]  (only first 32 used; row = 80B = 5*16B)
__device__ __align__(16) __nv_bfloat16 g_Ahp[(size_t)B_ * 8 * 256 * 40];
__device__ __align__(16) __nv_bfloat16 g_Alp[(size_t)B_ * 8 * 256 * 40];

// ---------------------------------------------------------------------------
// Helpers
// ---------------------------------------------------------------------------
__device__ __forceinline__ float warp_sum(float v) {
#pragma unroll
    for (int o = 16; o > 0; o >>= 1) v += __shfl_xor_sync(0xffffffffu, v, o);
    return v;
}
// pack: 'first' -> low 16 bits, 'second' -> high 16 bits
__device__ __forceinline__ uint32_t pack_bf16x2(float first, float second) {
    uint32_t r;
    asm("cvt.rn.bf16x2.f32 %0, %1, %2;" : "=r"(r) : "f"(second), "f"(first));
    return r;
}
__device__ __forceinline__ void mma_bf16(float* d, const uint32_t* a, const uint32_t* b) {
    asm volatile(
        "mma.sync.aligned.m16n8k16.row.col.f32.bf16.bf16.f32 "
        "{%0,%1,%2,%3}, {%4,%5,%6,%7}, {%8,%9}, {%0,%1,%2,%3};"
        : "+f"(d[0]), "+f"(d[1]), "+f"(d[2]), "+f"(d[3])
        : "r"(a[0]), "r"(a[1]), "r"(a[2]), "r"(a[3]), "r"(b[0]), "r"(b[1]));
}
__device__ __forceinline__ void cp16(uint32_t dst, const void* src) {
    asm volatile("cp.async.cg.shared.global [%0], [%1], 16;" :: "r"(dst), "l"(src));
}
#define CP_COMMIT() asm volatile("cp.async.commit_group;" ::: "memory")
#define CP_WAIT0()  asm volatile("cp.async.wait_group 0;" ::: "memory")

// ---------------------------------------------------------------------------
// Kernel 1: per-(b,c) sum / sumsq over 16384 pixels. 1 block per (b,c).
// ---------------------------------------------------------------------------
__global__ void stats_k(const float* __restrict__ x) {
    int bc = blockIdx.x;
    const float4* xp = (const float4*)(x + (size_t)bc * HW_);
    float s = 0.f, s2 = 0.f;
#pragma unroll
    for (int it = 0; it < 16; ++it) {
        float4 v = xp[threadIdx.x + it * 256];
        s  += v.x + v.y + v.z + v.w;
        s2 += v.x * v.x + v.y * v.y + v.z * v.z + v.w * v.w;
    }
    s = warp_sum(s); s2 = warp_sum(s2);
    __shared__ float sh[2][8];
    int w = threadIdx.x >> 5, l = threadIdx.x & 31;
    if (l == 0) { sh[0][w] = s; sh[1][w] = s2; }
    __syncthreads();
    if (threadIdx.x == 0) {
        float S = 0.f, S2 = 0.f;
#pragma unroll
        for (int i = 0; i < 8; ++i) { S += sh[0][i]; S2 += sh[1][i]; }
        g_sums[bc] = make_float2(S, S2);
    }
}

// ---------------------------------------------------------------------------
// Kernel 2: finalize IN / LN stats
// ---------------------------------------------------------------------------
__global__ void finalize_k() {
    int b = blockIdx.x, c = threadIdx.x;
    float2 sv = g_sums[b * C_ + c];
    const float inv = 1.0f / (float)HW_;
    float m = sv.x * inv;
    float v = fmaxf(sv.y * inv - m * m, 0.f);
    g_meanI[b * C_ + c] = m;
    g_rI[b * C_ + c]    = rsqrtf(v + EPS_);
    float s = warp_sum(sv.x), s2 = warp_sum(sv.y);
    __shared__ float sh[2][8];
    int w = c >> 5, l = c & 31;
    if (l == 0) { sh[0][w] = s; sh[1][w] = s2; }
    __syncthreads();
    if (c == 0) {
        float S = 0.f, S2 = 0.f;
#pragma unroll
        for (int i = 0; i < 8; ++i) { S += sh[0][i]; S2 += sh[1][i]; }
        const float invN = 1.0f / ((float)C_ * (float)HW_);
        float M = S * invN;
        float V = fmaxf(S2 * invN - M * M, 0.f);
        g_mlrl[b * 2]     = M;
        g_mlrl[b * 2 + 1] = rsqrtf(V + EPS_);
    }
}

// ---------------------------------------------------------------------------
// Kernel 3: build Aeff bf16 hi/lo (padded chunk layout) + bias.
// block=(b,o), thread=i(k)
// ---------------------------------------------------------------------------
__global__ void prep_k(const float* __restrict__ W,
                       const float* __restrict__ params) {
    int b = blockIdx.x >> 8;
    int o = blockIdx.x & 255;
    int i = threadIdx.x;

    float w1 = W[o * (2 * C_) + i];
    float w2 = W[o * (2 * C_) + C_ + i];
    float ri = g_rI[b * C_ + i];
    float mi = g_meanI[b * C_ + i];
    float ml = g_mlrl[b * 2];
    float rl = g_mlrl[b * 2 + 1];
    float gamma = params[b * (2 * C_) + o];
    float beta  = params[b * (2 * C_) + C_ + o];

    float a = gamma * (w1 * ri + w2 * rl);
    __nv_bfloat16 h = __float2bfloat16(a);
    float lo = a - __bfloat162float(h);
    // padded per-chunk layout: [b][c=i>>5][m=o][kk=i&31] row-stride 40
    size_t idx = (((size_t)b * 8 + (i >> 5)) * 256 + o) * 40 + (i & 31);
    g_Ahp[idx] = h;
    g_Alp[idx] = __float2bfloat16(lo);

    float p = w1 * ri * mi + w2 * rl * ml;
    p = warp_sum(p);
    __shared__ float sh[8];
    int w = i >> 5, l = i & 31;
    if (l == 0) sh[w] = p;
    __syncthreads();
    if (i == 0) {
        float P = 0.f;
#pragma unroll
        for (int j = 0; j < 8; ++j) P += sh[j];
        g_bias[b * C_ + o] = beta - gamma * P;
    }
}

// ---------------------------------------------------------------------------
// Kernel 4: mma.sync bf16 GEMM, cp.async-pipelined.
//   out[b][m][n] = sum_k Aeff[b][m][k] * x[b][k][n] + bias[b][m]
//   CTA: M=256, N=128 pixels, K=256 in 8 chunks of 32k (double-buffered A).
//   3-term split: Ah*xh + Al*xh + Ah*xl.
// SMEM word layout:
//   xh [n 128][128]  @ 0      xor-swizzled: word(n,kw)=n*128+(kw^((n&7)<<2)^((n>>3)&3))
//   xl               @ 16384
//   A double buffer  @ 32768  per buf: hi 256*20 + lo 256*20 = 10240 words
//   bias             @ 53248
// ---------------------------------------------------------------------------
#define OFF_XH   0
#define OFF_XL   16384
#define OFF_A    32768
#define OFF_BIAS 53248
#define SMEM_WORDS 53504
#define SMEM_BYTES (SMEM_WORDS * 4)
#define SAW 20   // A row stride (words) per 32-k chunk (16 data + 4 pad)

__global__ __launch_bounds__(256, 1)
void gemm_tc(const float* __restrict__ x, float* __restrict__ out) {
    extern __shared__ uint32_t sm[];
    uint32_t* s_xh = sm + OFF_XH;
    uint32_t* s_xl = sm + OFF_XL;
    float*    s_bias = (float*)(sm + OFF_BIAS);
    uint32_t smb = (uint32_t)__cvta_generic_to_shared(sm);

    int t = threadIdx.x;
    int b = blockIdx.y;
    int n0 = blockIdx.x << 7;
    int lane = t & 31, wid = t >> 5;

    const char* gAh = (const char*)g_Ahp + ((size_t)b * 8 * 256) * 80;
    const char* gAl = (const char*)g_Alp + ((size_t)b * 8 * 256) * 80;
    int cpm = t >> 2, cps = (t & 3) * 16;   // m-row, 16B-seg byte offset

    // Issue A chunk 0 -> buf 0 (overlaps the whole phase-1 x conversion)
#define ISSUE_CHUNK(c, buf) do {                                               \
        uint32_t dhi = smb + (OFF_A + (buf) * 10240) * 4;                      \
        uint32_t dlo = dhi + 5120 * 4;                                         \
        const char* sh_ = gAh + (size_t)(c) * 256 * 80;                        \
        const char* sl_ = gAl + (size_t)(c) * 256 * 80;                        \
        _Pragma("unroll")                                                      \
        for (int ps = 0; ps < 4; ++ps) {                                       \
            int m_ = cpm + ps * 64;                                            \
            cp16(dhi + (m_ * SAW) * 4 + cps, sh_ + m_ * 80 + cps);             \
            cp16(dlo + (m_ * SAW) * 4 + cps, sl_ + m_ * 80 + cps);             \
        }                                                                      \
        CP_COMMIT();                                                           \
    } while (0)

    ISSUE_CHUNK(0, 0);

    s_bias[t] = g_bias[b * C_ + t];

    // ---- Phase 1: x tile [256 k][128 n] -> bf16 hi/lo, swizzled smem ----
    {
        const float* xb = x + (size_t)b * C_ * HW_ + n0;
#pragma unroll 2
        for (int j = 0; j < 16; ++j) {
            int kw = wid * 16 + j;
            const float* r0 = xb + (size_t)(2 * kw) * HW_;
            const float* r1 = r0 + HW_;
            float f0[4], f1[4];
#pragma unroll
            for (int i = 0; i < 4; ++i) {
                f0[i] = r0[lane + 32 * i];
                f1[i] = r1[lane + 32 * i];
            }
#pragma unroll
            for (int i = 0; i < 4; ++i) {
                int n = lane + 32 * i;
                int col = kw ^ ((n & 7) << 2) ^ ((n >> 3) & 3);
                float g0 = f0[i] - __bfloat162float(__float2bfloat16(f0[i]));
                float g1 = f1[i] - __bfloat162float(__float2bfloat16(f1[i]));
                s_xh[n * 128 + col] = pack_bf16x2(f0[i], f1[i]);
                s_xl[n * 128 + col] = pack_bf16x2(g0, g1);
            }
        }
    }

    // ---- Phase 2: pipelined mainloop over 8 chunks of 32k ----
    int wm = wid >> 1;              // 0..3 -> 64 m rows
    int wn = wid & 1;               // 0..1 -> 64 n cols
    int gq = lane >> 2;             // 0..7
    int tg = lane & 3;              // 0..3
    int g4 = gq << 2;

    float acc[4][8][4];
#pragma unroll
    for (int i = 0; i < 4; ++i)
#pragma unroll
        for (int j = 0; j < 8; ++j)
#pragma unroll
            for (int q = 0; q < 4; ++q) acc[i][j][q] = 0.f;

    for (int c = 0; c < 8; ++c) {
        CP_WAIT0();
        __syncthreads();   // A buf (c&1) filled & visible; x ready (c==0)
        if (c < 7) ISSUE_CHUNK(c + 1, (c + 1) & 1);

        uint32_t* sAh = sm + OFF_A + (c & 1) * 10240;
        uint32_t* sAl = sAh + 5120;

#pragma unroll
        for (int ks = 0; ks < 2; ++ks) {
            int kwg = c * 16 + ks * 8 + tg;      // global k-pair for x
            int kwa = ks * 8 + tg;               // local k-pair for A

            uint32_t bh[8][2];
#pragma unroll
            for (int nt = 0; nt < 8; ++nt) {
                int n = wn * 64 + nt * 8 + gq;
                int c0 = kwg ^ g4 ^ (nt & 3);
                bh[nt][0] = s_xh[n * 128 + c0];
                bh[nt][1] = s_xh[n * 128 + (c0 ^ 4)];
            }
            uint32_t ah[4][4];
#pragma unroll
            for (int mt = 0; mt < 4; ++mt) {
                int w = (wm * 64 + mt * 16 + gq) * SAW + kwa;
                ah[mt][0] = sAh[w];
                ah[mt][1] = sAh[w + 8 * SAW];
                ah[mt][2] = sAh[w + 4];
                ah[mt][3] = sAh[w + 8 * SAW + 4];
            }
            // term 1: Ah * xh
#pragma unroll
            for (int mt = 0; mt < 4; ++mt)
#pragma unroll
                for (int nt = 0; nt < 8; ++nt)
                    mma_bf16(acc[mt][nt], ah[mt], bh[nt]);

            // term 2: Al * xh
            uint32_t al[4][4];
#pragma unroll
            for (int mt = 0; mt < 4; ++mt) {
                int w = (wm * 64 + mt * 16 + gq) * SAW + kwa;
                al[mt][0] = sAl[w];
                al[mt][1] = sAl[w + 8 * SAW];
                al[mt][2] = sAl[w + 4];
                al[mt][3] = sAl[w + 8 * SAW + 4];
            }
#pragma unroll
            for (int mt = 0; mt < 4; ++mt)
#pragma unroll
                for (int nt = 0; nt < 8; ++nt)
                    mma_bf16(acc[mt][nt], al[mt], bh[nt]);

            // term 3: Ah * xl (reuse bh regs)
#pragma unroll
            for (int nt = 0; nt < 8; ++nt) {
                int n = wn * 64 + nt * 8 + gq;
                int c0 = kwg ^ g4 ^ (nt & 3);
                bh[nt][0] = s_xl[n * 128 + c0];
                bh[nt][1] = s_xl[n * 128 + (c0 ^ 4)];
            }
#pragma unroll
            for (int mt = 0; mt < 4; ++mt)
#pragma unroll
                for (int nt = 0; nt < 8; ++nt)
                    mma_bf16(acc[mt][nt], ah[mt], bh[nt]);
        }
    }

    // ---- Phase 3: epilogue ----
#pragma unroll
    for (int mt = 0; mt < 4; ++mt) {
        int m = wm * 64 + mt * 16 + gq;
        float b0 = s_bias[m];
        float b1 = s_bias[m + 8];
#pragma unroll
        for (int nt = 0; nt < 8; ++nt) {
            int n = n0 + wn * 64 + nt * 8 + tg * 2;
            float* o0 = out + ((size_t)(b * C_ + m)) * HW_ + n;
            float2 v0 = make_float2(acc[mt][nt][0] + b0, acc[mt][nt][1] + b0);
            float2 v1 = make_float2(acc[mt][nt][2] + b1, acc[mt][nt][3] + b1);
            *(float2*)o0 = v0;
            *(float2*)(o0 + (size_t)8 * HW_) = v1;
        }
    }
}

// ---------------------------------------------------------------------------
// Launch
// ---------------------------------------------------------------------------
extern "C" void kernel_launch(void* const* d_in, const int* in_sizes, int n_in,
                              void* d_out, int out_size) {
    const float* x      = (const float*)d_in[0];
    const float* params = (const float*)d_in[1];
    const float* W      = (const float*)d_in[2];
    float* out = (float*)d_out;

    cudaFuncSetAttribute(gemm_tc, cudaFuncAttributeMaxDynamicSharedMemorySize,
                         SMEM_BYTES);

    stats_k<<<B_ * C_, 256>>>(x);
    finalize_k<<<B_, 256>>>();
    prep_k<<<B_ * C_, 256>>>(W, params);
    dim3 grid(HW_ / 128, B_);
    gemm_tc<<<grid, 256, SMEM_BYTES>>>(x, out);
}

// round 6
// speedup vs baseline: 1.6842x; 1.0425x over previous
#include <cuda_runtime.h>
#include <cuda_bf16.h>
#include <cstdint>
#include <cstddef>

#define B_   8
#define C_   256
#define HW_  16384
#define EPS_ 1e-5f

// ---------------------------------------------------------------------------
// Device scratch
// ---------------------------------------------------------------------------
__device__ float2 g_sums[B_ * C_];
__device__ float  g_meanI[B_ * C_];
__device__ float  g_rI[B_ * C_];
__device__ float  g_mlrl[B_ * 2];
__device__ float  g_bias[B_ * C_];
// Aeff bf16 hi/lo in padded per-chunk layout for linear cp.async:
//   [b][chunk(8)][m(256)][40 bf16]  (only first 32 used; row = 80B = 5*16B)
__device__ __align__(16) __nv_bfloat16 g_Ahp[(size_t)B_ * 8 * 256 * 40];
__device__ __align__(16) __nv_bfloat16 g_Alp[(size_t)B_ * 8 * 256 * 40];

// ---------------------------------------------------------------------------
// Helpers
// ---------------------------------------------------------------------------
__device__ __forceinline__ float warp_sum(float v) {
#pragma unroll
    for (int o = 16; o > 0; o >>= 1) v += __shfl_xor_sync(0xffffffffu, v, o);
    return v;
}
// pack: 'first' -> low 16 bits, 'second' -> high 16 bits
__device__ __forceinline__ uint32_t pack_bf16x2(float first, float second) {
    uint32_t r;
    asm("cvt.rn.bf16x2.f32 %0, %1, %2;" : "=r"(r) : "f"(second), "f"(first));
    return r;
}
__device__ __forceinline__ void mma_bf16(float* d, const uint32_t* a, const uint32_t* b) {
    asm volatile(
        "mma.sync.aligned.m16n8k16.row.col.f32.bf16.bf16.f32 "
        "{%0,%1,%2,%3}, {%4,%5,%6,%7}, {%8,%9}, {%0,%1,%2,%3};"
        : "+f"(d[0]), "+f"(d[1]), "+f"(d[2]), "+f"(d[3])
        : "r"(a[0]), "r"(a[1]), "r"(a[2]), "r"(a[3]), "r"(b[0]), "r"(b[1]));
}
__device__ __forceinline__ void cp16(uint32_t dst, const void* src) {
    asm volatile("cp.async.cg.shared.global [%0], [%1], 16;" :: "r"(dst), "l"(src));
}
#define CP_COMMIT() asm volatile("cp.async.commit_group;" ::: "memory")
#define CP_WAIT0()  asm volatile("cp.async.wait_group 0;" ::: "memory")

// ---------------------------------------------------------------------------
// Kernel 1: per-(b,c) sum / sumsq over 16384 pixels. 1 block per (b,c).
// ---------------------------------------------------------------------------
__global__ void stats_k(const float* __restrict__ x) {
    int bc = blockIdx.x;
    const float4* xp = (const float4*)(x + (size_t)bc * HW_);
    float s = 0.f, s2 = 0.f;
#pragma unroll
    for (int it = 0; it < 16; ++it) {
        float4 v = xp[threadIdx.x + it * 256];
        s  += v.x + v.y + v.z + v.w;
        s2 += v.x * v.x + v.y * v.y + v.z * v.z + v.w * v.w;
    }
    s = warp_sum(s); s2 = warp_sum(s2);
    __shared__ float sh[2][8];
    int w = threadIdx.x >> 5, l = threadIdx.x & 31;
    if (l == 0) { sh[0][w] = s; sh[1][w] = s2; }
    __syncthreads();
    if (threadIdx.x == 0) {
        float S = 0.f, S2 = 0.f;
#pragma unroll
        for (int i = 0; i < 8; ++i) { S += sh[0][i]; S2 += sh[1][i]; }
        g_sums[bc] = make_float2(S, S2);
    }
}

// ---------------------------------------------------------------------------
// Kernel 2: finalize IN / LN stats
// ---------------------------------------------------------------------------
__global__ void finalize_k() {
    int b = blockIdx.x, c = threadIdx.x;
    float2 sv = g_sums[b * C_ + c];
    const float inv = 1.0f / (float)HW_;
    float m = sv.x * inv;
    float v = fmaxf(sv.y * inv - m * m, 0.f);
    g_meanI[b * C_ + c] = m;
    g_rI[b * C_ + c]    = rsqrtf(v + EPS_);
    float s = warp_sum(sv.x), s2 = warp_sum(sv.y);
    __shared__ float sh[2][8];
    int w = c >> 5, l = c & 31;
    if (l == 0) { sh[0][w] = s; sh[1][w] = s2; }
    __syncthreads();
    if (c == 0) {
        float S = 0.f, S2 = 0.f;
#pragma unroll
        for (int i = 0; i < 8; ++i) { S += sh[0][i]; S2 += sh[1][i]; }
        const float invN = 1.0f / ((float)C_ * (float)HW_);
        float M = S * invN;
        float V = fmaxf(S2 * invN - M * M, 0.f);
        g_mlrl[b * 2]     = M;
        g_mlrl[b * 2 + 1] = rsqrtf(V + EPS_);
    }
}

// ---------------------------------------------------------------------------
// Kernel 3: build Aeff bf16 hi/lo (padded chunk layout) + bias.
// block=(b,o), thread=i(k)
// ---------------------------------------------------------------------------
__global__ void prep_k(const float* __restrict__ W,
                       const float* __restrict__ params) {
    int b = blockIdx.x >> 8;
    int o = blockIdx.x & 255;
    int i = threadIdx.x;

    float w1 = W[o * (2 * C_) + i];
    float w2 = W[o * (2 * C_) + C_ + i];
    float ri = g_rI[b * C_ + i];
    float mi = g_meanI[b * C_ + i];
    float ml = g_mlrl[b * 2];
    float rl = g_mlrl[b * 2 + 1];
    float gamma = params[b * (2 * C_) + o];
    float beta  = params[b * (2 * C_) + C_ + o];

    float a = gamma * (w1 * ri + w2 * rl);
    __nv_bfloat16 h = __float2bfloat16(a);
    float lo = a - __bfloat162float(h);
    // padded per-chunk layout: [b][c=i>>5][m=o][kk=i&31] row-stride 40
    size_t idx = (((size_t)b * 8 + (i >> 5)) * 256 + o) * 40 + (i & 31);
    g_Ahp[idx] = h;
    g_Alp[idx] = __float2bfloat16(lo);

    float p = w1 * ri * mi + w2 * rl * ml;
    p = warp_sum(p);
    __shared__ float sh[8];
    int w = i >> 5, l = i & 31;
    if (l == 0) sh[w] = p;
    __syncthreads();
    if (i == 0) {
        float P = 0.f;
#pragma unroll
        for (int j = 0; j < 8; ++j) P += sh[j];
        g_bias[b * C_ + o] = beta - gamma * P;
    }
}

// ---------------------------------------------------------------------------
// Kernel 4: mma.sync bf16 GEMM, cp.async-pipelined, 512 threads (16 warps).
//   out[b][m][n] = sum_k Aeff[b][m][k] * x[b][k][n] + bias[b][m]
//   CTA: M=256, N=128 pixels, K=256 in 8 chunks of 32k (double-buffered A).
//   Warp grid: 4 (m) x 4 (n): each warp 64m x 32n.
//   3-term split: Ah*xh + Al*xh + Ah*xl.
// SMEM word layout:
//   xh [n 128][128]  @ 0      xor-swizzled: word(n,kw)=n*128+(kw^((n&7)<<2)^((n>>3)&3))
//   xl               @ 16384
//   A double buffer  @ 32768  per buf: hi 256*20 + lo 256*20 = 10240 words
//   bias             @ 53248
// ---------------------------------------------------------------------------
#define OFF_XH   0
#define OFF_XL   16384
#define OFF_A    32768
#define OFF_BIAS 53248
#define SMEM_WORDS 53504
#define SMEM_BYTES (SMEM_WORDS * 4)
#define SAW 20   // A row stride (words) per 32-k chunk (16 data + 4 pad)

__global__ __launch_bounds__(512, 1)
void gemm_tc(const float* __restrict__ x, float* __restrict__ out) {
    extern __shared__ uint32_t sm[];
    uint32_t* s_xh = sm + OFF_XH;
    uint32_t* s_xl = sm + OFF_XL;
    float*    s_bias = (float*)(sm + OFF_BIAS);
    uint32_t smb = (uint32_t)__cvta_generic_to_shared(sm);

    int t = threadIdx.x;
    int b = blockIdx.y;
    int n0 = blockIdx.x << 7;
    int lane = t & 31, wid = t >> 5;

    const char* gAh = (const char*)g_Ahp + ((size_t)b * 8 * 256) * 80;
    const char* gAl = (const char*)g_Alp + ((size_t)b * 8 * 256) * 80;
    int cpm = t >> 2, cps = (t & 3) * 16;   // m-row (0..127), 16B-seg byte offset

    // Copy A chunk c -> smem buf (512 threads: each 2 rows x 1 seg, hi+lo)
#define ISSUE_CHUNK(c, buf) do {                                               \
        uint32_t dhi = smb + (OFF_A + (buf) * 10240) * 4;                      \
        uint32_t dlo = dhi + 5120 * 4;                                         \
        const char* sh_ = gAh + (size_t)(c) * 256 * 80;                        \
        const char* sl_ = gAl + (size_t)(c) * 256 * 80;                        \
        _Pragma("unroll")                                                      \
        for (int ps = 0; ps < 2; ++ps) {                                       \
            int m_ = cpm + ps * 128;                                           \
            cp16(dhi + (m_ * SAW) * 4 + cps, sh_ + m_ * 80 + cps);             \
            cp16(dlo + (m_ * SAW) * 4 + cps, sl_ + m_ * 80 + cps);             \
        }                                                                      \
        CP_COMMIT();                                                           \
    } while (0)

    ISSUE_CHUNK(0, 0);

    if (t < 256) s_bias[t] = g_bias[b * C_ + t];

    // ---- Phase 1: x tile [256 k][128 n] -> bf16 hi/lo, swizzled smem ----
    {
        const float* xb = x + (size_t)b * C_ * HW_ + n0;
#pragma unroll 2
        for (int j = 0; j < 8; ++j) {
            int kw = wid * 8 + j;
            const float* r0 = xb + (size_t)(2 * kw) * HW_;
            const float* r1 = r0 + HW_;
            float f0[4], f1[4];
#pragma unroll
            for (int i = 0; i < 4; ++i) {
                f0[i] = r0[lane + 32 * i];
                f1[i] = r1[lane + 32 * i];
            }
#pragma unroll
            for (int i = 0; i < 4; ++i) {
                int n = lane + 32 * i;
                int col = kw ^ ((n & 7) << 2) ^ ((n >> 3) & 3);
                float g0 = f0[i] - __bfloat162float(__float2bfloat16(f0[i]));
                float g1 = f1[i] - __bfloat162float(__float2bfloat16(f1[i]));
                s_xh[n * 128 + col] = pack_bf16x2(f0[i], f1[i]);
                s_xl[n * 128 + col] = pack_bf16x2(g0, g1);
            }
        }
    }

    // ---- Phase 2: pipelined mainloop over 8 chunks of 32k ----
    int wm = wid >> 2;              // 0..3 -> 64 m rows
    int wn = wid & 3;               // 0..3 -> 32 n cols
    int gq = lane >> 2;             // 0..7
    int tg = lane & 3;              // 0..3
    int g4 = gq << 2;

    float acc[4][4][4];
#pragma unroll
    for (int i = 0; i < 4; ++i)
#pragma unroll
        for (int j = 0; j < 4; ++j)
#pragma unroll
            for (int q = 0; q < 4; ++q) acc[i][j][q] = 0.f;

    for (int c = 0; c < 8; ++c) {
        CP_WAIT0();
        __syncthreads();   // A buf (c&1) filled & visible; x ready (c==0)
        if (c < 7) ISSUE_CHUNK(c + 1, (c + 1) & 1);

        uint32_t* sAh = sm + OFF_A + (c & 1) * 10240;
        uint32_t* sAl = sAh + 5120;

#pragma unroll
        for (int ks = 0; ks < 2; ++ks) {
            int kwg = c * 16 + ks * 8 + tg;      // global k-pair for x
            int kwa = ks * 8 + tg;               // local k-pair for A

            uint32_t bh[4][2];
#pragma unroll
            for (int nt = 0; nt < 4; ++nt) {
                int n = wn * 32 + nt * 8 + gq;
                int c0 = kwg ^ g4 ^ (nt & 3);
                bh[nt][0] = s_xh[n * 128 + c0];
                bh[nt][1] = s_xh[n * 128 + (c0 ^ 4)];
            }
            uint32_t ah[4][4];
#pragma unroll
            for (int mt = 0; mt < 4; ++mt) {
                int w = (wm * 64 + mt * 16 + gq) * SAW + kwa;
                ah[mt][0] = sAh[w];
                ah[mt][1] = sAh[w + 8 * SAW];
                ah[mt][2] = sAh[w + 4];
                ah[mt][3] = sAh[w + 8 * SAW + 4];
            }
            // term 1: Ah * xh
#pragma unroll
            for (int mt = 0; mt < 4; ++mt)
#pragma unroll
                for (int nt = 0; nt < 4; ++nt)
                    mma_bf16(acc[mt][nt], ah[mt], bh[nt]);

            // term 2: Al * xh
            uint32_t al[4][4];
#pragma unroll
            for (int mt = 0; mt < 4; ++mt) {
                int w = (wm * 64 + mt * 16 + gq) * SAW + kwa;
                al[mt][0] = sAl[w];
                al[mt][1] = sAl[w + 8 * SAW];
                al[mt][2] = sAl[w + 4];
                al[mt][3] = sAl[w + 8 * SAW + 4];
            }
#pragma unroll
            for (int mt = 0; mt < 4; ++mt)
#pragma unroll
                for (int nt = 0; nt < 4; ++nt)
                    mma_bf16(acc[mt][nt], al[mt], bh[nt]);

            // term 3: Ah * xl (reuse bh regs)
#pragma unroll
            for (int nt = 0; nt < 4; ++nt) {
                int n = wn * 32 + nt * 8 + gq;
                int c0 = kwg ^ g4 ^ (nt & 3);
                bh[nt][0] = s_xl[n * 128 + c0];
                bh[nt][1] = s_xl[n * 128 + (c0 ^ 4)];
            }
#pragma unroll
            for (int mt = 0; mt < 4; ++mt)
#pragma unroll
                for (int nt = 0; nt < 4; ++nt)
                    mma_bf16(acc[mt][nt], ah[mt], bh[nt]);
        }
    }

    // ---- Phase 3: epilogue ----
#pragma unroll
    for (int mt = 0; mt < 4; ++mt) {
        int m = wm * 64 + mt * 16 + gq;
        float b0 = s_bias[m];
        float b1 = s_bias[m + 8];
#pragma unroll
        for (int nt = 0; nt < 4; ++nt) {
            int n = n0 + wn * 32 + nt * 8 + tg * 2;
            float* o0 = out + ((size_t)(b * C_ + m)) * HW_ + n;
            float2 v0 = make_float2(acc[mt][nt][0] + b0, acc[mt][nt][1] + b0);
            float2 v1 = make_float2(acc[mt][nt][2] + b1, acc[mt][nt][3] + b1);
            *(float2*)o0 = v0;
            *(float2*)(o0 + (size_t)8 * HW_) = v1;
        }
    }
}

// ---------------------------------------------------------------------------
// Launch
// ---------------------------------------------------------------------------
extern "C" void kernel_launch(void* const* d_in, const int* in_sizes, int n_in,
                              void* d_out, int out_size) {
    const float* x      = (const float*)d_in[0];
    const float* params = (const float*)d_in[1];
    const float* W      = (const float*)d_in[2];
    float* out = (float*)d_out;

    cudaFuncSetAttribute(gemm_tc, cudaFuncAttributeMaxDynamicSharedMemorySize,
                         SMEM_BYTES);

    stats_k<<<B_ * C_, 256>>>(x);
    finalize_k<<<B_, 256>>>();
    prep_k<<<B_ * C_, 256>>>(W, params);
    dim3 grid(HW_ / 128, B_);
    gemm_tc<<<grid, 512, SMEM_BYTES>>>(x, out);
}

// round 7
// speedup vs baseline: 1.9485x; 1.1569x over previous
#include <cuda_runtime.h>
#include <cuda_fp16.h>
#include <cstdint>
#include <cstddef>

#define B_   8
#define C_   256
#define HW_  16384
#define EPS_ 1e-5f

// ---------------------------------------------------------------------------
// Device scratch
// ---------------------------------------------------------------------------
__device__ float2 g_sums[B_ * C_];
__device__ float  g_meanI[B_ * C_];
__device__ float  g_rI[B_ * C_];
__device__ float  g_mlrl[B_ * 2];
__device__ float  g_bias[B_ * C_];
// Aeff fp16 (single copy), padded per-chunk layout for linear cp.async:
//   [b][chunk(4)][m(256)][72 fp16]  (first 64 used; row = 144B = 9*16B)
__device__ __align__(16) __half g_Afp[(size_t)B_ * 4 * 256 * 72];

// ---------------------------------------------------------------------------
// Helpers
// ---------------------------------------------------------------------------
__device__ __forceinline__ float warp_sum(float v) {
#pragma unroll
    for (int o = 16; o > 0; o >>= 1) v += __shfl_xor_sync(0xffffffffu, v, o);
    return v;
}
__device__ __forceinline__ void mma_fp16(float* d, const uint32_t* a, const uint32_t* b) {
    asm volatile(
        "mma.sync.aligned.m16n8k16.row.col.f32.f16.f16.f32 "
        "{%0,%1,%2,%3}, {%4,%5,%6,%7}, {%8,%9}, {%0,%1,%2,%3};"
        : "+f"(d[0]), "+f"(d[1]), "+f"(d[2]), "+f"(d[3])
        : "r"(a[0]), "r"(a[1]), "r"(a[2]), "r"(a[3]), "r"(b[0]), "r"(b[1]));
}
__device__ __forceinline__ void cp16(uint32_t dst, const void* src) {
    asm volatile("cp.async.cg.shared.global [%0], [%1], 16;" :: "r"(dst), "l"(src));
}
#define CP_COMMIT() asm volatile("cp.async.commit_group;" ::: "memory")
#define CP_WAIT0()  asm volatile("cp.async.wait_group 0;" ::: "memory")

// ---------------------------------------------------------------------------
// Kernel 1: per-(b,c) sum / sumsq over 16384 pixels. 1 block per (b,c).
// ---------------------------------------------------------------------------
__global__ void stats_k(const float* __restrict__ x) {
    int bc = blockIdx.x;
    const float4* xp = (const float4*)(x + (size_t)bc * HW_);
    float s = 0.f, s2 = 0.f;
#pragma unroll
    for (int it = 0; it < 16; ++it) {
        float4 v = xp[threadIdx.x + it * 256];
        s  += v.x + v.y + v.z + v.w;
        s2 += v.x * v.x + v.y * v.y + v.z * v.z + v.w * v.w;
    }
    s = warp_sum(s); s2 = warp_sum(s2);
    __shared__ float sh[2][8];
    int w = threadIdx.x >> 5, l = threadIdx.x & 31;
    if (l == 0) { sh[0][w] = s; sh[1][w] = s2; }
    __syncthreads();
    if (threadIdx.x == 0) {
        float S = 0.f, S2 = 0.f;
#pragma unroll
        for (int i = 0; i < 8; ++i) { S += sh[0][i]; S2 += sh[1][i]; }
        g_sums[bc] = make_float2(S, S2);
    }
}

// ---------------------------------------------------------------------------
// Kernel 2: finalize IN / LN stats
// ---------------------------------------------------------------------------
__global__ void finalize_k() {
    int b = blockIdx.x, c = threadIdx.x;
    float2 sv = g_sums[b * C_ + c];
    const float inv = 1.0f / (float)HW_;
    float m = sv.x * inv;
    float v = fmaxf(sv.y * inv - m * m, 0.f);
    g_meanI[b * C_ + c] = m;
    g_rI[b * C_ + c]    = rsqrtf(v + EPS_);
    float s = warp_sum(sv.x), s2 = warp_sum(sv.y);
    __shared__ float sh[2][8];
    int w = c >> 5, l = c & 31;
    if (l == 0) { sh[0][w] = s; sh[1][w] = s2; }
    __syncthreads();
    if (c == 0) {
        float S = 0.f, S2 = 0.f;
#pragma unroll
        for (int i = 0; i < 8; ++i) { S += sh[0][i]; S2 += sh[1][i]; }
        const float invN = 1.0f / ((float)C_ * (float)HW_);
        float M = S * invN;
        float V = fmaxf(S2 * invN - M * M, 0.f);
        g_mlrl[b * 2]     = M;
        g_mlrl[b * 2 + 1] = rsqrtf(V + EPS_);
    }
}

// ---------------------------------------------------------------------------
// Kernel 3: build Aeff fp16 (padded chunk layout) + bias.
// block=(b,o), thread=i(k)
// ---------------------------------------------------------------------------
__global__ void prep_k(const float* __restrict__ W,
                       const float* __restrict__ params) {
    int b = blockIdx.x >> 8;
    int o = blockIdx.x & 255;
    int i = threadIdx.x;

    float w1 = W[o * (2 * C_) + i];
    float w2 = W[o * (2 * C_) + C_ + i];
    float ri = g_rI[b * C_ + i];
    float mi = g_meanI[b * C_ + i];
    float ml = g_mlrl[b * 2];
    float rl = g_mlrl[b * 2 + 1];
    float gamma = params[b * (2 * C_) + o];
    float beta  = params[b * (2 * C_) + C_ + o];

    float a = gamma * (w1 * ri + w2 * rl);
    // padded per-chunk layout: [b][c=i>>6][m=o][kk=i&63] row-stride 72
    size_t idx = (((size_t)b * 4 + (i >> 6)) * 256 + o) * 72 + (i & 63);
    g_Afp[idx] = __float2half_rn(a);

    float p = w1 * ri * mi + w2 * rl * ml;
    p = warp_sum(p);
    __shared__ float sh[8];
    int w = i >> 5, l = i & 31;
    if (l == 0) sh[w] = p;
    __syncthreads();
    if (i == 0) {
        float P = 0.f;
#pragma unroll
        for (int j = 0; j < 8; ++j) P += sh[j];
        g_bias[b * C_ + o] = beta - gamma * P;
    }
}

// ---------------------------------------------------------------------------
// Kernel 4: mma.sync fp16 GEMM, cp.async-pipelined, 512 threads (16 warps).
//   out[b][m][n] = sum_k Aeff[b][m][k] * x[b][k][n] + bias[b][m]
//   CTA: M=256, N=128 pixels, K=256 in 4 chunks of 64k (double-buffered A).
//   Warp grid: 4 (m) x 4 (n): each warp 64m x 32n.
//   2-term split: A*xh + A*xl  (A fp16, err ~2.8e-4 norm-rel).
// SMEM word layout:
//   xh [n 128][128]  @ 0      xor-swizzled: word(n,kw)=n*128+(kw^((n&7)<<2)^((n>>3)&3))
//   xl               @ 16384
//   A double buffer  @ 32768  per buf: 256 rows * 36 words = 9216 words (36KB)
//   bias             @ 51200
// ---------------------------------------------------------------------------
#define OFF_XH   0
#define OFF_XL   16384
#define OFF_A    32768
#define OFF_BIAS 51200
#define SMEM_WORDS 51456
#define SMEM_BYTES (SMEM_WORDS * 4)
#define SAW 36   // A row stride (words) per 64-k chunk (32 data + 4 pad)

__global__ __launch_bounds__(512, 1)
void gemm_tc(const float* __restrict__ x, float* __restrict__ out) {
    extern __shared__ uint32_t sm[];
    uint32_t* s_xh = sm + OFF_XH;
    uint32_t* s_xl = sm + OFF_XL;
    float*    s_bias = (float*)(sm + OFF_BIAS);
    uint32_t smb = (uint32_t)__cvta_generic_to_shared(sm);

    int t = threadIdx.x;
    int b = blockIdx.y;
    int n0 = blockIdx.x << 7;
    int lane = t & 31, wid = t >> 5;

    const char* gA = (const char*)g_Afp + ((size_t)b * 4 * 256) * 144;
    // copy mapping: row = t>>1 (0..255), half t&1: segs [0,4) or [4,9)
    int cprow  = t >> 1;
    int cps0   = (t & 1) * 4;
    int cpsN   = (t & 1) ? 9 : 4;

#define ISSUE_CHUNK(c, buf) do {                                               \
        uint32_t d0 = smb + (OFF_A + (buf) * 9216) * 4 + cprow * (SAW * 4);    \
        const char* s0 = gA + (size_t)(c) * 256 * 144 + cprow * 144;           \
        _Pragma("unroll")                                                      \
        for (int s = cps0; s < cpsN; ++s)                                      \
            cp16(d0 + s * 16, s0 + s * 16);                                    \
        CP_COMMIT();                                                           \
    } while (0)

    ISSUE_CHUNK(0, 0);

    if (t < 256) s_bias[t] = g_bias[b * C_ + t];

    // ---- Phase 1: x tile [256 k][128 n] -> fp16 hi/lo, swizzled smem ----
    {
        const float* xb = x + (size_t)b * C_ * HW_ + n0;
#pragma unroll 2
        for (int j = 0; j < 8; ++j) {
            int kw = wid * 8 + j;
            const float* r0 = xb + (size_t)(2 * kw) * HW_;
            const float* r1 = r0 + HW_;
            float f0[4], f1[4];
#pragma unroll
            for (int i = 0; i < 4; ++i) {
                f0[i] = r0[lane + 32 * i];
                f1[i] = r1[lane + 32 * i];
            }
#pragma unroll
            for (int i = 0; i < 4; ++i) {
                int n = lane + 32 * i;
                int col = kw ^ ((n & 7) << 2) ^ ((n >> 3) & 3);
                __half h0 = __float2half_rn(f0[i]);
                __half h1 = __float2half_rn(f1[i]);
                float g0 = f0[i] - __half2float(h0);
                float g1 = f1[i] - __half2float(h1);
                __half2 hv = __halves2half2(h0, h1);            // low = k even
                __half2 lv = __floats2half2_rn(g0, g1);
                s_xh[n * 128 + col] = *(uint32_t*)&hv;
                s_xl[n * 128 + col] = *(uint32_t*)&lv;
            }
        }
    }

    // ---- Phase 2: pipelined mainloop over 4 chunks of 64k ----
    int wm = wid >> 2;              // 0..3 -> 64 m rows
    int wn = wid & 3;               // 0..3 -> 32 n cols
    int gq = lane >> 2;             // 0..7
    int tg = lane & 3;              // 0..3
    int g4 = gq << 2;

    float acc[4][4][4];
#pragma unroll
    for (int i = 0; i < 4; ++i)
#pragma unroll
        for (int j = 0; j < 4; ++j)
#pragma unroll
            for (int q = 0; q < 4; ++q) acc[i][j][q] = 0.f;

    for (int c = 0; c < 4; ++c) {
        CP_WAIT0();
        __syncthreads();   // A buf (c&1) filled & visible; x ready (c==0)
        if (c < 3) ISSUE_CHUNK(c + 1, (c + 1) & 1);

        uint32_t* sA = sm + OFF_A + (c & 1) * 9216;

#pragma unroll
        for (int ks = 0; ks < 4; ++ks) {
            int kwg = c * 32 + ks * 8 + tg;      // global k-pair word for x
            int kwa = ks * 8 + tg;               // local k-pair word for A

            uint32_t ah[4][4];
#pragma unroll
            for (int mt = 0; mt < 4; ++mt) {
                int w = (wm * 64 + mt * 16 + gq) * SAW + kwa;
                ah[mt][0] = sA[w];
                ah[mt][1] = sA[w + 8 * SAW];
                ah[mt][2] = sA[w + 4];
                ah[mt][3] = sA[w + 8 * SAW + 4];
            }
            uint32_t bh[4][2];
#pragma unroll
            for (int nt = 0; nt < 4; ++nt) {
                int n = wn * 32 + nt * 8 + gq;
                int c0 = kwg ^ g4 ^ (nt & 3);
                bh[nt][0] = s_xh[n * 128 + c0];
                bh[nt][1] = s_xh[n * 128 + (c0 ^ 4)];
            }
            // term 1: A * xh
#pragma unroll
            for (int mt = 0; mt < 4; ++mt)
#pragma unroll
                for (int nt = 0; nt < 4; ++nt)
                    mma_fp16(acc[mt][nt], ah[mt], bh[nt]);

            // term 2: A * xl (reuse bh regs)
#pragma unroll
            for (int nt = 0; nt < 4; ++nt) {
                int n = wn * 32 + nt * 8 + gq;
                int c0 = kwg ^ g4 ^ (nt & 3);
                bh[nt][0] = s_xl[n * 128 + c0];
                bh[nt][1] = s_xl[n * 128 + (c0 ^ 4)];
            }
#pragma unroll
            for (int mt = 0; mt < 4; ++mt)
#pragma unroll
                for (int nt = 0; nt < 4; ++nt)
                    mma_fp16(acc[mt][nt], ah[mt], bh[nt]);
        }
    }

    // ---- Phase 3: epilogue ----
#pragma unroll
    for (int mt = 0; mt < 4; ++mt) {
        int m = wm * 64 + mt * 16 + gq;
        float b0 = s_bias[m];
        float b1 = s_bias[m + 8];
#pragma unroll
        for (int nt = 0; nt < 4; ++nt) {
            int n = n0 + wn * 32 + nt * 8 + tg * 2;
            float* o0 = out + ((size_t)(b * C_ + m)) * HW_ + n;
            float2 v0 = make_float2(acc[mt][nt][0] + b0, acc[mt][nt][1] + b0);
            float2 v1 = make_float2(acc[mt][nt][2] + b1, acc[mt][nt][3] + b1);
            *(float2*)o0 = v0;
            *(float2*)(o0 + (size_t)8 * HW_) = v1;
        }
    }
}

// ---------------------------------------------------------------------------
// Launch
// ---------------------------------------------------------------------------
extern "C" void kernel_launch(void* const* d_in, const int* in_sizes, int n_in,
                              void* d_out, int out_size) {
    const float* x      = (const float*)d_in[0];
    const float* params = (const float*)d_in[1];
    const float* W      = (const float*)d_in[2];
    float* out = (float*)d_out;

    cudaFuncSetAttribute(gemm_tc, cudaFuncAttributeMaxDynamicSharedMemorySize,
                         SMEM_BYTES);

    stats_k<<<B_ * C_, 256>>>(x);
    finalize_k<<<B_, 256>>>();
    prep_k<<<B_ * C_, 256>>>(W, params);
    dim3 grid(HW_ / 128, B_);
    gemm_tc<<<grid, 512, SMEM_BYTES>>>(x, out);
}

// round 10
// speedup vs baseline: 2.0316x; 1.0427x over previous
#include <cuda_runtime.h>
#include <cuda_fp16.h>
#include <cstdint>
#include <cstddef>

#define B_   8
#define C_   256
#define HW_  16384
#define EPS_ 1e-5f

// ---------------------------------------------------------------------------
// Device scratch
// ---------------------------------------------------------------------------
__device__ float2 g_sums[B_ * C_];
__device__ float  g_meanI[B_ * C_];
__device__ float  g_rI[B_ * C_];
__device__ float  g_mlrl[B_ * 2];
__device__ float  g_bias[B_ * C_];
// Aeff fp16 (single copy), padded per-chunk layout for linear cp.async:
//   [b][chunk(4)][m(256)][72 fp16]  (first 64 used; row = 144B = 9*16B)
__device__ __align__(16) __half g_Afp[(size_t)B_ * 4 * 256 * 72];

// ---------------------------------------------------------------------------
// Helpers
// ---------------------------------------------------------------------------
__device__ __forceinline__ float warp_sum(float v) {
#pragma unroll
    for (int o = 16; o > 0; o >>= 1) v += __shfl_xor_sync(0xffffffffu, v, o);
    return v;
}
__device__ __forceinline__ void mma_fp16(float* d, const uint32_t* a, const uint32_t* b) {
    asm volatile(
        "mma.sync.aligned.m16n8k16.row.col.f32.f16.f16.f32 "
        "{%0,%1,%2,%3}, {%4,%5,%6,%7}, {%8,%9}, {%0,%1,%2,%3};"
        : "+f"(d[0]), "+f"(d[1]), "+f"(d[2]), "+f"(d[3])
        : "r"(a[0]), "r"(a[1]), "r"(a[2]), "r"(a[3]), "r"(b[0]), "r"(b[1]));
}
__device__ __forceinline__ void cp16(uint32_t dst, const void* src) {
    asm volatile("cp.async.cg.shared.global [%0], [%1], 16;" :: "r"(dst), "l"(src));
}
#define CP_COMMIT() asm volatile("cp.async.commit_group;" ::: "memory")
#define CP_WAIT0()  asm volatile("cp.async.wait_group 0;" ::: "memory")

// ---------------------------------------------------------------------------
// Kernel 1: per-(b,c) sum / sumsq over 16384 pixels. 1 block per (b,c).
// ---------------------------------------------------------------------------
__global__ void stats_k(const float* __restrict__ x) {
    int bc = blockIdx.x;
    const float4* xp = (const float4*)(x + (size_t)bc * HW_);
    float s = 0.f, s2 = 0.f;
#pragma unroll
    for (int it = 0; it < 16; ++it) {
        float4 v = xp[threadIdx.x + it * 256];
        s  += v.x + v.y + v.z + v.w;
        s2 += v.x * v.x + v.y * v.y + v.z * v.z + v.w * v.w;
    }
    s = warp_sum(s); s2 = warp_sum(s2);
    __shared__ float sh[2][8];
    int w = threadIdx.x >> 5, l = threadIdx.x & 31;
    if (l == 0) { sh[0][w] = s; sh[1][w] = s2; }
    __syncthreads();
    if (threadIdx.x == 0) {
        float S = 0.f, S2 = 0.f;
#pragma unroll
        for (int i = 0; i < 8; ++i) { S += sh[0][i]; S2 += sh[1][i]; }
        g_sums[bc] = make_float2(S, S2);
    }
}

// ---------------------------------------------------------------------------
// Kernel 2: finalize IN / LN stats
// ---------------------------------------------------------------------------
__global__ void finalize_k() {
    int b = blockIdx.x, c = threadIdx.x;
    float2 sv = g_sums[b * C_ + c];
    const float inv = 1.0f / (float)HW_;
    float m = sv.x * inv;
    float v = fmaxf(sv.y * inv - m * m, 0.f);
    g_meanI[b * C_ + c] = m;
    g_rI[b * C_ + c]    = rsqrtf(v + EPS_);
    float s = warp_sum(sv.x), s2 = warp_sum(sv.y);
    __shared__ float sh[2][8];
    int w = c >> 5, l = c & 31;
    if (l == 0) { sh[0][w] = s; sh[1][w] = s2; }
    __syncthreads();
    if (c == 0) {
        float S = 0.f, S2 = 0.f;
#pragma unroll
        for (int i = 0; i < 8; ++i) { S += sh[0][i]; S2 += sh[1][i]; }
        const float invN = 1.0f / ((float)C_ * (float)HW_);
        float M = S * invN;
        float V = fmaxf(S2 * invN - M * M, 0.f);
        g_mlrl[b * 2]     = M;
        g_mlrl[b * 2 + 1] = rsqrtf(V + EPS_);
    }
}

// ---------------------------------------------------------------------------
// Kernel 3: build Aeff fp16 (padded chunk layout) + bias.
// block=(b,o), thread=i(k)
// ---------------------------------------------------------------------------
__global__ void prep_k(const float* __restrict__ W,
                       const float* __restrict__ params) {
    int b = blockIdx.x >> 8;
    int o = blockIdx.x & 255;
    int i = threadIdx.x;

    float w1 = W[o * (2 * C_) + i];
    float w2 = W[o * (2 * C_) + C_ + i];
    float ri = g_rI[b * C_ + i];
    float mi = g_meanI[b * C_ + i];
    float ml = g_mlrl[b * 2];
    float rl = g_mlrl[b * 2 + 1];
    float gamma = params[b * (2 * C_) + o];
    float beta  = params[b * (2 * C_) + C_ + o];

    float a = gamma * (w1 * ri + w2 * rl);
    // padded per-chunk layout: [b][c=i>>6][m=o][kk=i&63] row-stride 72
    size_t idx = (((size_t)b * 4 + (i >> 6)) * 256 + o) * 72 + (i & 63);
    g_Afp[idx] = __float2half_rn(a);

    float p = w1 * ri * mi + w2 * rl * ml;
    p = warp_sum(p);
    __shared__ float sh[8];
    int w = i >> 5, l = i & 31;
    if (l == 0) sh[w] = p;
    __syncthreads();
    if (i == 0) {
        float P = 0.f;
#pragma unroll
        for (int j = 0; j < 8; ++j) P += sh[j];
        g_bias[b * C_ + o] = beta - gamma * P;
    }
}

// ---------------------------------------------------------------------------
// Kernel 4: mma.sync fp16 GEMM, fully software-pipelined (A via cp.async,
// x via LDG->cvt->STS interleaved under the MMAs), 512 threads / 16 warps.
//   out[b][m][n] = sum_k Aeff[b][m][k] * x[b][k][n] + bias[b][m]
//   CTA: M=256, N=128 pixels, K=256 in 4 chunks of 64k, both operands
//   double-buffered. 2-term split: A*xh + A*xl.
// SMEM word layout:
//   x double buf @ 0: per buf [n 128][32 cols] hi then lo
//       word(n,kwl) = n*32 + (kwl ^ ((n&7)<<2) ^ ((n>>3)&3))
//       buf stride 8192 words; hi at +0, lo at +4096
//   A double buf @ 16384: per buf 256 rows * 36 words = 9216 words
//   bias @ 34816
// ---------------------------------------------------------------------------
#define OFF_X    0
#define OFF_A    16384
#define OFF_BIAS 34816
#define SMEM_WORDS 35072
#define SMEM_BYTES (SMEM_WORDS * 4)
#define SAW 36   // A row stride (words) per 64-k chunk (32 data + 4 pad)

__global__ __launch_bounds__(512, 1)
void gemm_tc(const float* __restrict__ x, float* __restrict__ out) {
    extern __shared__ uint32_t sm[];
    float* s_bias = (float*)(sm + OFF_BIAS);
    uint32_t smb = (uint32_t)__cvta_generic_to_shared(sm);

    int t = threadIdx.x;
    int b = blockIdx.y;
    int n0 = blockIdx.x << 7;
    int lane = t & 31, wid = t >> 5;

    const float* xb = x + (size_t)b * C_ * HW_ + n0;
    const char* gA = (const char*)g_Afp + ((size_t)b * 4 * 256) * 144;
    // A copy mapping: row = t>>1 (0..255), half t&1: segs [0,4) or [4,9)
    int cprow = t >> 1;
    int cps0  = (t & 1) * 4;
    int cpsN  = (t & 1) ? 9 : 4;

#define ISSUE_A(c, buf) do {                                                   \
        uint32_t d0 = smb + (OFF_A + (buf) * 9216) * 4 + cprow * (SAW * 4);    \
        const char* s0 = gA + (size_t)(c) * 256 * 144 + cprow * 144;           \
        _Pragma("unroll")                                                      \
        for (int s = cps0; s < cpsN; ++s)                                      \
            cp16(d0 + s * 16, s0 + s * 16);                                    \
        CP_COMMIT();                                                           \
    } while (0)

    // x chunk conversion: 16 warps x 2 kwl-rows; lane covers 4 n each row.
    float f0[2][4], f1[2][4];
#define LOAD_X(c) do {                                                         \
        _Pragma("unroll")                                                      \
        for (int j = 0; j < 2; ++j) {                                          \
            int kwg = (c) * 32 + wid * 2 + j;                                  \
            const float* r0 = xb + (size_t)(2 * kwg) * HW_;                    \
            const float* r1 = r0 + HW_;                                        \
            _Pragma("unroll")                                                  \
            for (int i = 0; i < 4; ++i) {                                      \
                f0[j][i] = r0[lane + 32 * i];                                  \
                f1[j][i] = r1[lane + 32 * i];                                  \
            }                                                                  \
        }                                                                      \
    } while (0)

#define STORE_X(buf) do {                                                      \
        uint32_t* sxh = sm + OFF_X + (buf) * 8192;                             \
        uint32_t* sxl = sxh + 4096;                                            \
        _Pragma("unroll")                                                      \
        for (int j = 0; j < 2; ++j) {                                          \
            int kwl = wid * 2 + j;                                             \
            _Pragma("unroll")                                                  \
            for (int i = 0; i < 4; ++i) {                                      \
                int n = lane + 32 * i;                                         \
                int col = kwl ^ ((n & 7) << 2) ^ ((n >> 3) & 3);               \
                __half h0 = __float2half_rn(f0[j][i]);                         \
                __half h1 = __float2half_rn(f1[j][i]);                         \
                float g0 = f0[j][i] - __half2float(h0);                        \
                float g1 = f1[j][i] - __half2float(h1);                        \
                __half2 hv = __halves2half2(h0, h1);                           \
                __half2 lv = __floats2half2_rn(g0, g1);                        \
                sxh[n * 32 + col] = *(uint32_t*)&hv;                           \
                sxl[n * 32 + col] = *(uint32_t*)&lv;                           \
            }                                                                  \
        }                                                                      \
    } while (0)

    // ---- Prologue: A chunk 0 + x chunk 0 ----
    ISSUE_A(0, 0);
    if (t < 256) s_bias[t] = g_bias[b * C_ + t];
    LOAD_X(0);
    STORE_X(0);

    // ---- Mainloop ----
    int wm = wid >> 2;              // 0..3 -> 64 m rows
    int wn = wid & 3;               // 0..3 -> 32 n cols
    int gq = lane >> 2;             // 0..7
    int tg = lane & 3;              // 0..3

    float acc[4][4][4];
#pragma unroll
    for (int i = 0; i < 4; ++i)
#pragma unroll
        for (int j = 0; j < 4; ++j)
#pragma unroll
            for (int q = 0; q < 4; ++q) acc[i][j][q] = 0.f;

    for (int c = 0; c < 4; ++c) {
        CP_WAIT0();
        __syncthreads();   // A buf (c&1) + x buf (c&1) visible
        if (c < 3) {
            ISSUE_A(c + 1, (c + 1) & 1);
            LOAD_X(c + 1);             // LDGs in flight under the MMAs below
        }

        uint32_t* sA  = sm + OFF_A + (c & 1) * 9216;
        uint32_t* sxh = sm + OFF_X + (c & 1) * 8192;
        uint32_t* sxl = sxh + 4096;

#pragma unroll
        for (int ks = 0; ks < 4; ++ks) {
            int kwl = ks * 8 + tg;               // chunk-local k-pair word

            uint32_t ah[4][4];
#pragma unroll
            for (int mt = 0; mt < 4; ++mt) {
                int w = (wm * 64 + mt * 16 + gq) * SAW + kwl;
                ah[mt][0] = sA[w];
                ah[mt][1] = sA[w + 8 * SAW];
                ah[mt][2] = sA[w + 4];
                ah[mt][3] = sA[w + 8 * SAW + 4];
            }
            uint32_t bh[4][2];
#pragma unroll
            for (int nt = 0; nt < 4; ++nt) {
                int n = wn * 32 + nt * 8 + gq;
                int c0 = kwl ^ ((n & 7) << 2) ^ ((n >> 3) & 3);
                bh[nt][0] = sxh[n * 32 + c0];
                bh[nt][1] = sxh[n * 32 + (c0 ^ 4)];
            }
            // term 1: A * xh
#pragma unroll
            for (int mt = 0; mt < 4; ++mt)
#pragma unroll
                for (int nt = 0; nt < 4; ++nt)
                    mma_fp16(acc[mt][nt], ah[mt], bh[nt]);

            // term 2: A * xl (reuse bh regs)
#pragma unroll
            for (int nt = 0; nt < 4; ++nt) {
                int n = wn * 32 + nt * 8 + gq;
                int c0 = kwl ^ ((n & 7) << 2) ^ ((n >> 3) & 3);
                bh[nt][0] = sxl[n * 32 + c0];
                bh[nt][1] = sxl[n * 32 + (c0 ^ 4)];
            }
#pragma unroll
            for (int mt = 0; mt < 4; ++mt)
#pragma unroll
                for (int nt = 0; nt < 4; ++nt)
                    mma_fp16(acc[mt][nt], ah[mt], bh[nt]);
        }

        if (c < 3) STORE_X((c + 1) & 1);   // cvt+STS after MMAs; next sync orders
    }

    // ---- Epilogue ----
#pragma unroll
    for (int mt = 0; mt < 4; ++mt) {
        int m = wm * 64 + mt * 16 + gq;
        float b0 = s_bias[m];
        float b1 = s_bias[m + 8];
#pragma unroll
        for (int nt = 0; nt < 4; ++nt) {
            int n = n0 + wn * 32 + nt * 8 + tg * 2;
            float* o0 = out + ((size_t)(b * C_ + m)) * HW_ + n;
            float2 v0 = make_float2(acc[mt][nt][0] + b0, acc[mt][nt][1] + b0);
            float2 v1 = make_float2(acc[mt][nt][2] + b1, acc[mt][nt][3] + b1);
            *(float2*)o0 = v0;
            *(float2*)(o0 + (size_t)8 * HW_) = v1;
        }
    }
}

// ---------------------------------------------------------------------------
// Launch
// ---------------------------------------------------------------------------
extern "C" void kernel_launch(void* const* d_in, const int* in_sizes, int n_in,
                              void* d_out, int out_size) {
    const float* x      = (const float*)d_in[0];
    const float* params = (const float*)d_in[1];
    const float* W      = (const float*)d_in[2];
    float* out = (float*)d_out;

    cudaFuncSetAttribute(gemm_tc, cudaFuncAttributeMaxDynamicSharedMemorySize,
                         SMEM_BYTES);

    stats_k<<<B_ * C_, 256>>>(x);
    finalize_k<<<B_, 256>>>();
    prep_k<<<B_ * C_, 256>>>(W, params);
    dim3 grid(HW_ / 128, B_);
    gemm_tc<<<grid, 512, SMEM_BYTES>>>(x, out);
}

// round 12
// speedup vs baseline: 2.1477x; 1.0572x over previous
#include <cuda_runtime.h>
#include <cuda_fp16.h>
#include <cstdint>
#include <cstddef>

#define B_   8
#define C_   256
#define HW_  16384
#define EPS_ 1e-5f

// ---------------------------------------------------------------------------
// Device scratch
// ---------------------------------------------------------------------------
__device__ float2 g_sums[B_ * C_];
__device__ float  g_meanI[B_ * C_];
__device__ float  g_rI[B_ * C_];
__device__ float  g_mlrl[B_ * 2];
__device__ float  g_bias[B_ * C_];
// Aeff fp16 (single copy), padded per-chunk layout for linear cp.async:
//   [b][chunk(4)][m(256)][72 fp16]  (first 64 used; row = 144B = 9*16B)
__device__ __align__(16) __half g_Afp[(size_t)B_ * 4 * 256 * 72];

// ---------------------------------------------------------------------------
// Helpers
// ---------------------------------------------------------------------------
__device__ __forceinline__ float warp_sum(float v) {
#pragma unroll
    for (int o = 16; o > 0; o >>= 1) v += __shfl_xor_sync(0xffffffffu, v, o);
    return v;
}
__device__ __forceinline__ void mma_fp16(float* d, const uint32_t* a, const uint32_t* b) {
    asm volatile(
        "mma.sync.aligned.m16n8k16.row.col.f32.f16.f16.f32 "
        "{%0,%1,%2,%3}, {%4,%5,%6,%7}, {%8,%9}, {%0,%1,%2,%3};"
        : "+f"(d[0]), "+f"(d[1]), "+f"(d[2]), "+f"(d[3])
        : "r"(a[0]), "r"(a[1]), "r"(a[2]), "r"(a[3]), "r"(b[0]), "r"(b[1]));
}
__device__ __forceinline__ void cp16(uint32_t dst, const void* src) {
    asm volatile("cp.async.cg.shared.global [%0], [%1], 16;" :: "r"(dst), "l"(src));
}
#define CP_COMMIT() asm volatile("cp.async.commit_group;" ::: "memory")
#define CP_WAIT0()  asm volatile("cp.async.wait_group 0;" ::: "memory")

// ---------------------------------------------------------------------------
// Kernel 1: per-(b,c) sum / sumsq over 16384 pixels. 1 block per (b,c).
// ---------------------------------------------------------------------------
__global__ void stats_k(const float* __restrict__ x) {
    int bc = blockIdx.x;
    const float4* xp = (const float4*)(x + (size_t)bc * HW_);
    float s = 0.f, s2 = 0.f;
#pragma unroll
    for (int it = 0; it < 16; ++it) {
        float4 v = xp[threadIdx.x + it * 256];
        s  += v.x + v.y + v.z + v.w;
        s2 += v.x * v.x + v.y * v.y + v.z * v.z + v.w * v.w;
    }
    s = warp_sum(s); s2 = warp_sum(s2);
    __shared__ float sh[2][8];
    int w = threadIdx.x >> 5, l = threadIdx.x & 31;
    if (l == 0) { sh[0][w] = s; sh[1][w] = s2; }
    __syncthreads();
    if (threadIdx.x == 0) {
        float S = 0.f, S2 = 0.f;
#pragma unroll
        for (int i = 0; i < 8; ++i) { S += sh[0][i]; S2 += sh[1][i]; }
        g_sums[bc] = make_float2(S, S2);
    }
}

// ---------------------------------------------------------------------------
// Kernel 2: finalize IN / LN stats
// ---------------------------------------------------------------------------
__global__ void finalize_k() {
    int b = blockIdx.x, c = threadIdx.x;
    float2 sv = g_sums[b * C_ + c];
    const float inv = 1.0f / (float)HW_;
    float m = sv.x * inv;
    float v = fmaxf(sv.y * inv - m * m, 0.f);
    g_meanI[b * C_ + c] = m;
    g_rI[b * C_ + c]    = rsqrtf(v + EPS_);
    float s = warp_sum(sv.x), s2 = warp_sum(sv.y);
    __shared__ float sh[2][8];
    int w = c >> 5, l = c & 31;
    if (l == 0) { sh[0][w] = s; sh[1][w] = s2; }
    __syncthreads();
    if (c == 0) {
        float S = 0.f, S2 = 0.f;
#pragma unroll
        for (int i = 0; i < 8; ++i) { S += sh[0][i]; S2 += sh[1][i]; }
        const float invN = 1.0f / ((float)C_ * (float)HW_);
        float M = S * invN;
        float V = fmaxf(S2 * invN - M * M, 0.f);
        g_mlrl[b * 2]     = M;
        g_mlrl[b * 2 + 1] = rsqrtf(V + EPS_);
    }
}

// ---------------------------------------------------------------------------
// Kernel 3: build Aeff fp16 (padded chunk layout) + bias.
// block=(b,o), thread=i(k)
// ---------------------------------------------------------------------------
__global__ void prep_k(const float* __restrict__ W,
                       const float* __restrict__ params) {
    int b = blockIdx.x >> 8;
    int o = blockIdx.x & 255;
    int i = threadIdx.x;

    float w1 = W[o * (2 * C_) + i];
    float w2 = W[o * (2 * C_) + C_ + i];
    float ri = g_rI[b * C_ + i];
    float mi = g_meanI[b * C_ + i];
    float ml = g_mlrl[b * 2];
    float rl = g_mlrl[b * 2 + 1];
    float gamma = params[b * (2 * C_) + o];
    float beta  = params[b * (2 * C_) + C_ + o];

    float a = gamma * (w1 * ri + w2 * rl);
    // padded per-chunk layout: [b][c=i>>6][m=o][kk=i&63] row-stride 72
    size_t idx = (((size_t)b * 4 + (i >> 6)) * 256 + o) * 72 + (i & 63);
    g_Afp[idx] = __float2half_rn(a);

    float p = w1 * ri * mi + w2 * rl * ml;
    p = warp_sum(p);
    __shared__ float sh[8];
    int w = i >> 5, l = i & 31;
    if (l == 0) sh[w] = p;
    __syncthreads();
    if (i == 0) {
        float P = 0.f;
#pragma unroll
        for (int j = 0; j < 8; ++j) P += sh[j];
        g_bias[b * C_ + o] = beta - gamma * P;
    }
}

// ---------------------------------------------------------------------------
// Kernel 4: mma.sync fp16 GEMM, 2 CTAs/SM (256 threads, 8 warps each).
//   CTA: M=128 (m-half = blockIdx.z), N=128 pixels, K=256 in 4 chunks of 64k.
//   Warp grid 2m x 4n, warp tile 64m x 32n. 2-term split: A*xh + A*xl.
//   x conversion pipelined in two half-loads per chunk to cap registers.
// SMEM word layout:
//   x double buf @ 0: per buf [n 128][32 cols] hi @ +0, lo @ +4096
//       word(n,kwl) = n*32 + (kwl ^ ((n&7)<<2) ^ ((n>>3)&3)); buf stride 8192
//   A double buf @ 16384: per buf 128 rows * 36 words = 4608 words
//   bias @ 25600 (128 floats)
// ---------------------------------------------------------------------------
#define OFF_X    0
#define OFF_A    16384
#define OFF_BIAS 25600
#define SMEM_WORDS 25728
#define SMEM_BYTES (SMEM_WORDS * 4)
#define SAW 36   // A row stride (words) per 64-k chunk (32 data + 4 pad)

__global__ __launch_bounds__(256, 2)
void gemm_tc(const float* __restrict__ x, float* __restrict__ out) {
    extern __shared__ uint32_t sm[];
    float* s_bias = (float*)(sm + OFF_BIAS);
    uint32_t smb = (uint32_t)__cvta_generic_to_shared(sm);

    int t = threadIdx.x;
    int b = blockIdx.y;
    int n0 = blockIdx.x << 7;
    int mh = blockIdx.z;            // m-half: 0 or 1
    int lane = t & 31, wid = t >> 5;

    const float* xb = x + (size_t)b * C_ * HW_ + n0;
    const char* gA = (const char*)g_Afp + ((size_t)b * 4 * 256) * 144
                   + (size_t)mh * 128 * 144;
    // A copy: row = t>>1 (0..127), half t&1: segs [0,4) or [4,9)
    int cprow = t >> 1;
    int cps0  = (t & 1) * 4;
    int cpsN  = (t & 1) ? 9 : 4;

#define ISSUE_A(c, buf) do {                                                   \
        uint32_t d0 = smb + (OFF_A + (buf) * 4608) * 4 + cprow * (SAW * 4);    \
        const char* s0 = gA + (size_t)(c) * 256 * 144 + cprow * 144;           \
        _Pragma("unroll")                                                      \
        for (int s = cps0; s < cpsN; ++s)                                      \
            cp16(d0 + s * 16, s0 + s * 16);                                    \
        CP_COMMIT();                                                           \
    } while (0)

    // x conversion: 8 warps x 4 kwl-rows per chunk, processed in 2 halves.
    float f0[2][4], f1[2][4];
#define LOAD_XH(c, h) do {                                                     \
        _Pragma("unroll")                                                      \
        for (int j = 0; j < 2; ++j) {                                          \
            int kwg = (c) * 32 + wid * 4 + (h) * 2 + j;                        \
            const float* r0 = xb + (size_t)(2 * kwg) * HW_;                    \
            const float* r1 = r0 + HW_;                                        \
            _Pragma("unroll")                                                  \
            for (int i = 0; i < 4; ++i) {                                      \
                f0[j][i] = r0[lane + 32 * i];                                  \
                f1[j][i] = r1[lane + 32 * i];                                  \
            }                                                                  \
        }                                                                      \
    } while (0)

#define STORE_XH(buf, h) do {                                                  \
        uint32_t* sxh = sm + OFF_X + (buf) * 8192;                             \
        uint32_t* sxl = sxh + 4096;                                            \
        _Pragma("unroll")                                                      \
        for (int j = 0; j < 2; ++j) {                                          \
            int kwl = wid * 4 + (h) * 2 + j;                                   \
            _Pragma("unroll")                                                  \
            for (int i = 0; i < 4; ++i) {                                      \
                int n = lane + 32 * i;                                         \
                int col = kwl ^ ((n & 7) << 2) ^ ((n >> 3) & 3);               \
                __half h0 = __float2half_rn(f0[j][i]);                         \
                __half h1 = __float2half_rn(f1[j][i]);                         \
                float g0 = f0[j][i] - __half2float(h0);                        \
                float g1 = f1[j][i] - __half2float(h1);                        \
                __half2 hv = __halves2half2(h0, h1);                           \
                __half2 lv = __floats2half2_rn(g0, g1);                        \
                sxh[n * 32 + col] = *(uint32_t*)&hv;                           \
                sxl[n * 32 + col] = *(uint32_t*)&lv;                           \
            }                                                                  \
        }                                                                      \
    } while (0)

    // ---- Prologue: A chunk 0 + x chunk 0 ----
    ISSUE_A(0, 0);
    if (t < 128) s_bias[t] = g_bias[b * C_ + mh * 128 + t];
    LOAD_XH(0, 0); STORE_XH(0, 0);
    LOAD_XH(0, 1); STORE_XH(0, 1);

    // ---- Mainloop ----
    int wm = wid >> 2;              // 0..1 -> 64 m rows
    int wn = wid & 3;               // 0..3 -> 32 n cols
    int gq = lane >> 2;             // 0..7
    int tg = lane & 3;              // 0..3

    float acc[4][4][4];
#pragma unroll
    for (int i = 0; i < 4; ++i)
#pragma unroll
        for (int j = 0; j < 4; ++j)
#pragma unroll
            for (int q = 0; q < 4; ++q) acc[i][j][q] = 0.f;

    // one ks-step of MMAs (2 terms)
#define MMA_STEP(ks, sA, sxh, sxl) do {                                        \
        int kwl = (ks) * 8 + tg;                                               \
        uint32_t ah[4][4];                                                     \
        _Pragma("unroll")                                                      \
        for (int mt = 0; mt < 4; ++mt) {                                       \
            int w = (wm * 64 + mt * 16 + gq) * SAW + kwl;                      \
            ah[mt][0] = (sA)[w];                                               \
            ah[mt][1] = (sA)[w + 8 * SAW];                                     \
            ah[mt][2] = (sA)[w + 4];                                           \
            ah[mt][3] = (sA)[w + 8 * SAW + 4];                                 \
        }                                                                      \
        uint32_t bh[4][2];                                                     \
        _Pragma("unroll")                                                      \
        for (int nt = 0; nt < 4; ++nt) {                                       \
            int n = wn * 32 + nt * 8 + gq;                                     \
            int c0 = kwl ^ ((n & 7) << 2) ^ ((n >> 3) & 3);                    \
            bh[nt][0] = (sxh)[n * 32 + c0];                                    \
            bh[nt][1] = (sxh)[n * 32 + (c0 ^ 4)];                              \
        }                                                                      \
        _Pragma("unroll")                                                      \
        for (int mt = 0; mt < 4; ++mt)                                         \
            _Pragma("unroll")                                                  \
            for (int nt = 0; nt < 4; ++nt)                                     \
                mma_fp16(acc[mt][nt], ah[mt], bh[nt]);                         \
        _Pragma("unroll")                                                      \
        for (int nt = 0; nt < 4; ++nt) {                                       \
            int n = wn * 32 + nt * 8 + gq;                                     \
            int c0 = kwl ^ ((n & 7) << 2) ^ ((n >> 3) & 3);                    \
            bh[nt][0] = (sxl)[n * 32 + c0];                                    \
            bh[nt][1] = (sxl)[n * 32 + (c0 ^ 4)];                              \
        }                                                                      \
        _Pragma("unroll")                                                      \
        for (int mt = 0; mt < 4; ++mt)                                         \
            _Pragma("unroll")                                                  \
            for (int nt = 0; nt < 4; ++nt)                                     \
                mma_fp16(acc[mt][nt], ah[mt], bh[nt]);                         \
    } while (0)

    for (int c = 0; c < 4; ++c) {
        CP_WAIT0();
        __syncthreads();   // A buf (c&1) + x buf (c&1) visible
        int nb = (c + 1) & 1;
        if (c < 3) {
            ISSUE_A(c + 1, nb);
            LOAD_XH(c + 1, 0);          // LDGs fly under ks 0-1 MMAs
        }

        uint32_t* sA  = sm + OFF_A + (c & 1) * 4608;
        uint32_t* sxh = sm + OFF_X + (c & 1) * 8192;
        uint32_t* sxl = sxh + 4096;

        MMA_STEP(0, sA, sxh, sxl);
        MMA_STEP(1, sA, sxh, sxl);

        if (c < 3) {
            STORE_XH(nb, 0);            // buf nb free: reads done before top sync
            LOAD_XH(c + 1, 1);          // LDGs fly under ks 2-3 MMAs
        }

        MMA_STEP(2, sA, sxh, sxl);
        MMA_STEP(3, sA, sxh, sxl);

        if (c < 3) STORE_XH(nb, 1);     // next top sync orders before reads
    }

    // ---- Epilogue ----
#pragma unroll
    for (int mt = 0; mt < 4; ++mt) {
        int m = wm * 64 + mt * 16 + gq;
        float b0 = s_bias[m];
        float b1 = s_bias[m + 8];
        int mg = mh * 128 + m;
#pragma unroll
        for (int nt = 0; nt < 4; ++nt) {
            int n = n0 + wn * 32 + nt * 8 + tg * 2;
            float* o0 = out + ((size_t)(b * C_ + mg)) * HW_ + n;
            float2 v0 = make_float2(acc[mt][nt][0] + b0, acc[mt][nt][1] + b0);
            float2 v1 = make_float2(acc[mt][nt][2] + b1, acc[mt][nt][3] + b1);
            *(float2*)o0 = v0;
            *(float2*)(o0 + (size_t)8 * HW_) = v1;
        }
    }
}

// ---------------------------------------------------------------------------
// Launch
// ---------------------------------------------------------------------------
extern "C" void kernel_launch(void* const* d_in, const int* in_sizes, int n_in,
                              void* d_out, int out_size) {
    const float* x      = (const float*)d_in[0];
    const float* params = (const float*)d_in[1];
    const float* W      = (const float*)d_in[2];
    float* out = (float*)d_out;

    cudaFuncSetAttribute(gemm_tc, cudaFuncAttributeMaxDynamicSharedMemorySize,
                         SMEM_BYTES);

    stats_k<<<B_ * C_, 256>>>(x);
    finalize_k<<<B_, 256>>>();
    prep_k<<<B_ * C_, 256>>>(W, params);
    dim3 grid(HW_ / 128, B_, 2);
    gemm_tc<<<grid, 256, SMEM_BYTES>>>(x, out);
}

// round 13
// speedup vs baseline: 2.7391x; 1.2754x over previous
#include <cuda_runtime.h>
#include <cuda_fp16.h>
#include <cstdint>
#include <cstddef>

#define B_   8
#define C_   256
#define HW_  16384
#define EPS_ 1e-5f

// ---------------------------------------------------------------------------
// Device scratch
// ---------------------------------------------------------------------------
__device__ float2 g_sums[B_ * C_];
__device__ float  g_meanI[B_ * C_];
__device__ float  g_rI[B_ * C_];
__device__ float  g_mlrl[B_ * 2];
__device__ float  g_bias[B_ * C_];
// Aeff fp16 (single copy), padded per-chunk layout for linear cp.async:
//   [b][chunk(4)][m(256)][72 fp16]  (first 64 used; row = 144B = 9*16B)
__device__ __align__(16) __half g_Afp[(size_t)B_ * 4 * 256 * 72];

// ---------------------------------------------------------------------------
// Helpers
// ---------------------------------------------------------------------------
__device__ __forceinline__ float warp_sum(float v) {
#pragma unroll
    for (int o = 16; o > 0; o >>= 1) v += __shfl_xor_sync(0xffffffffu, v, o);
    return v;
}
__device__ __forceinline__ void mma_fp16(float* d, const uint32_t* a, const uint32_t* b) {
    asm volatile(
        "mma.sync.aligned.m16n8k16.row.col.f32.f16.f16.f32 "
        "{%0,%1,%2,%3}, {%4,%5,%6,%7}, {%8,%9}, {%0,%1,%2,%3};"
        : "+f"(d[0]), "+f"(d[1]), "+f"(d[2]), "+f"(d[3])
        : "r"(a[0]), "r"(a[1]), "r"(a[2]), "r"(a[3]), "r"(b[0]), "r"(b[1]));
}
__device__ __forceinline__ void cp16(uint32_t dst, const void* src) {
    asm volatile("cp.async.cg.shared.global [%0], [%1], 16;" :: "r"(dst), "l"(src));
}
#define CP_COMMIT() asm volatile("cp.async.commit_group;" ::: "memory")
#define CP_WAIT0()  asm volatile("cp.async.wait_group 0;" ::: "memory")

// ---------------------------------------------------------------------------
// Kernel 1: per-(b,c) sum / sumsq over 16384 pixels. 1 block per (b,c).
// ---------------------------------------------------------------------------
__global__ void stats_k(const float* __restrict__ x) {
    int bc = blockIdx.x;
    const float4* xp = (const float4*)(x + (size_t)bc * HW_);
    float s = 0.f, s2 = 0.f;
#pragma unroll
    for (int it = 0; it < 16; ++it) {
        float4 v = xp[threadIdx.x + it * 256];
        s  += v.x + v.y + v.z + v.w;
        s2 += v.x * v.x + v.y * v.y + v.z * v.z + v.w * v.w;
    }
    s = warp_sum(s); s2 = warp_sum(s2);
    __shared__ float sh[2][8];
    int w = threadIdx.x >> 5, l = threadIdx.x & 31;
    if (l == 0) { sh[0][w] = s; sh[1][w] = s2; }
    __syncthreads();
    if (threadIdx.x == 0) {
        float S = 0.f, S2 = 0.f;
#pragma unroll
        for (int i = 0; i < 8; ++i) { S += sh[0][i]; S2 += sh[1][i]; }
        g_sums[bc] = make_float2(S, S2);
    }
}

// ---------------------------------------------------------------------------
// Kernel 2: finalize IN / LN stats
// ---------------------------------------------------------------------------
__global__ void finalize_k() {
    int b = blockIdx.x, c = threadIdx.x;
    float2 sv = g_sums[b * C_ + c];
    const float inv = 1.0f / (float)HW_;
    float m = sv.x * inv;
    float v = fmaxf(sv.y * inv - m * m, 0.f);
    g_meanI[b * C_ + c] = m;
    g_rI[b * C_ + c]    = rsqrtf(v + EPS_);
    float s = warp_sum(sv.x), s2 = warp_sum(sv.y);
    __shared__ float sh[2][8];
    int w = c >> 5, l = c & 31;
    if (l == 0) { sh[0][w] = s; sh[1][w] = s2; }
    __syncthreads();
    if (c == 0) {
        float S = 0.f, S2 = 0.f;
#pragma unroll
        for (int i = 0; i < 8; ++i) { S += sh[0][i]; S2 += sh[1][i]; }
        const float invN = 1.0f / ((float)C_ * (float)HW_);
        float M = S * invN;
        float V = fmaxf(S2 * invN - M * M, 0.f);
        g_mlrl[b * 2]     = M;
        g_mlrl[b * 2 + 1] = rsqrtf(V + EPS_);
    }
}

// ---------------------------------------------------------------------------
// Kernel 3: build Aeff fp16 (padded chunk layout) + bias.
// block=(b,o), thread=i(k)
// ---------------------------------------------------------------------------
__global__ void prep_k(const float* __restrict__ W,
                       const float* __restrict__ params) {
    int b = blockIdx.x >> 8;
    int o = blockIdx.x & 255;
    int i = threadIdx.x;

    float w1 = W[o * (2 * C_) + i];
    float w2 = W[o * (2 * C_) + C_ + i];
    float ri = g_rI[b * C_ + i];
    float mi = g_meanI[b * C_ + i];
    float ml = g_mlrl[b * 2];
    float rl = g_mlrl[b * 2 + 1];
    float gamma = params[b * (2 * C_) + o];
    float beta  = params[b * (2 * C_) + C_ + o];

    float a = gamma * (w1 * ri + w2 * rl);
    // padded per-chunk layout: [b][c=i>>6][m=o][kk=i&63] row-stride 72
    size_t idx = (((size_t)b * 4 + (i >> 6)) * 256 + o) * 72 + (i & 63);
    g_Afp[idx] = __float2half_rn(a);

    float p = w1 * ri * mi + w2 * rl * ml;
    p = warp_sum(p);
    __shared__ float sh[8];
    int w = i >> 5, l = i & 31;
    if (l == 0) sh[w] = p;
    __syncthreads();
    if (i == 0) {
        float P = 0.f;
#pragma unroll
        for (int j = 0; j < 8; ++j) P += sh[j];
        g_bias[b * C_ + o] = beta - gamma * P;
    }
}

// ---------------------------------------------------------------------------
// Kernel 4: mma.sync fp16 GEMM, 2 CTAs/SM, single-term fp16 (A and x fp16).
//   CTA: M=128 (m-half), N=128 pixels, K=256 in 4 chunks of 64k.
//   Grid x interleaves mh so the 2 CTAs sharing an x tile are adjacent (L2 reuse).
//   Warp grid 2m x 4n, warp tile 64m x 32n.
// SMEM word layout:
//   x double buf @ 0: per buf [n 128][32 cols]
//       word(n,kwl) = n*32 + (kwl ^ ((n&7)<<2) ^ ((n>>3)&3)); buf stride 4096
//   A double buf @ 8192: per buf 128 rows * 36 words = 4608 words
//   bias @ 17408 (128 floats)
// ---------------------------------------------------------------------------
#define OFF_X    0
#define OFF_A    8192
#define OFF_BIAS 17408
#define SMEM_WORDS 17536
#define SMEM_BYTES (SMEM_WORDS * 4)
#define SAW 36   // A row stride (words) per 64-k chunk (32 data + 4 pad)

__global__ __launch_bounds__(256, 2)
void gemm_tc(const float* __restrict__ x, float* __restrict__ out) {
    extern __shared__ uint32_t sm[];
    float* s_bias = (float*)(sm + OFF_BIAS);
    uint32_t smb = (uint32_t)__cvta_generic_to_shared(sm);

    int t = threadIdx.x;
    int b = blockIdx.y;
    int mh = blockIdx.x & 1;              // m-half (adjacent CTAs share x tile)
    int n0 = (blockIdx.x >> 1) << 7;
    int lane = t & 31, wid = t >> 5;

    const float* xb = x + (size_t)b * C_ * HW_ + n0;
    const char* gA = (const char*)g_Afp + ((size_t)b * 4 * 256) * 144
                   + (size_t)mh * 128 * 144;
    // A copy: row = t>>1 (0..127), half t&1: segs [0,4) or [4,9)
    int cprow = t >> 1;
    int cps0  = (t & 1) * 4;
    int cpsN  = (t & 1) ? 9 : 4;

#define ISSUE_A(c, buf) do {                                                   \
        uint32_t d0 = smb + (OFF_A + (buf) * 4608) * 4 + cprow * (SAW * 4);    \
        const char* s0 = gA + (size_t)(c) * 256 * 144 + cprow * 144;           \
        _Pragma("unroll")                                                      \
        for (int s = cps0; s < cpsN; ++s)                                      \
            cp16(d0 + s * 16, s0 + s * 16);                                    \
        CP_COMMIT();                                                           \
    } while (0)

    // x conversion: 8 warps x 4 kwl-rows per chunk, processed in 2 halves.
    float f0[2][4], f1[2][4];
#define LOAD_XH(c, h) do {                                                     \
        _Pragma("unroll")                                                      \
        for (int j = 0; j < 2; ++j) {                                          \
            int kwg = (c) * 32 + wid * 4 + (h) * 2 + j;                        \
            const float* r0 = xb + (size_t)(2 * kwg) * HW_;                    \
            const float* r1 = r0 + HW_;                                        \
            _Pragma("unroll")                                                  \
            for (int i = 0; i < 4; ++i) {                                      \
                f0[j][i] = r0[lane + 32 * i];                                  \
                f1[j][i] = r1[lane + 32 * i];                                  \
            }                                                                  \
        }                                                                      \
    } while (0)

#define STORE_XH(buf, h) do {                                                  \
        uint32_t* sx = sm + OFF_X + (buf) * 4096;                              \
        _Pragma("unroll")                                                      \
        for (int j = 0; j < 2; ++j) {                                          \
            int kwl = wid * 4 + (h) * 2 + j;                                   \
            _Pragma("unroll")                                                  \
            for (int i = 0; i < 4; ++i) {                                      \
                int n = lane + 32 * i;                                         \
                int col = kwl ^ ((n & 7) << 2) ^ ((n >> 3) & 3);               \
                __half2 hv = __floats2half2_rn(f0[j][i], f1[j][i]);            \
                sx[n * 32 + col] = *(uint32_t*)&hv;                            \
            }                                                                  \
        }                                                                      \
    } while (0)

    // ---- Prologue: A chunk 0 + x chunk 0 ----
    ISSUE_A(0, 0);
    if (t < 128) s_bias[t] = g_bias[b * C_ + mh * 128 + t];
    LOAD_XH(0, 0); STORE_XH(0, 0);
    LOAD_XH(0, 1); STORE_XH(0, 1);

    // ---- Mainloop ----
    int wm = wid >> 2;              // 0..1 -> 64 m rows
    int wn = wid & 3;               // 0..3 -> 32 n cols
    int gq = lane >> 2;             // 0..7
    int tg = lane & 3;              // 0..3

    float acc[4][4][4];
#pragma unroll
    for (int i = 0; i < 4; ++i)
#pragma unroll
        for (int j = 0; j < 4; ++j)
#pragma unroll
            for (int q = 0; q < 4; ++q) acc[i][j][q] = 0.f;

    // one ks-step: 16 MMAs (single fp16 term)
#define MMA_STEP(ks, sA, sx) do {                                              \
        int kwl = (ks) * 8 + tg;                                               \
        uint32_t ah[4][4];                                                     \
        _Pragma("unroll")                                                      \
        for (int mt = 0; mt < 4; ++mt) {                                       \
            int w = (wm * 64 + mt * 16 + gq) * SAW + kwl;                      \
            ah[mt][0] = (sA)[w];                                               \
            ah[mt][1] = (sA)[w + 8 * SAW];                                     \
            ah[mt][2] = (sA)[w + 4];                                           \
            ah[mt][3] = (sA)[w + 8 * SAW + 4];                                 \
        }                                                                      \
        uint32_t bh[4][2];                                                     \
        _Pragma("unroll")                                                      \
        for (int nt = 0; nt < 4; ++nt) {                                       \
            int n = wn * 32 + nt * 8 + gq;                                     \
            int c0 = kwl ^ ((n & 7) << 2) ^ ((n >> 3) & 3);                    \
            bh[nt][0] = (sx)[n * 32 + c0];                                     \
            bh[nt][1] = (sx)[n * 32 + (c0 ^ 4)];                               \
        }                                                                      \
        _Pragma("unroll")                                                      \
        for (int mt = 0; mt < 4; ++mt)                                         \
            _Pragma("unroll")                                                  \
            for (int nt = 0; nt < 4; ++nt)                                     \
                mma_fp16(acc[mt][nt], ah[mt], bh[nt]);                         \
    } while (0)

    for (int c = 0; c < 4; ++c) {
        CP_WAIT0();
        __syncthreads();   // A buf (c&1) + x buf (c&1) visible
        int nb = (c + 1) & 1;
        if (c < 3) {
            ISSUE_A(c + 1, nb);
            LOAD_XH(c + 1, 0);          // LDGs fly under ks 0-1 MMAs
        }

        uint32_t* sA = sm + OFF_A + (c & 1) * 4608;
        uint32_t* sx = sm + OFF_X + (c & 1) * 4096;

        MMA_STEP(0, sA, sx);
        MMA_STEP(1, sA, sx);

        if (c < 3) {
            STORE_XH(nb, 0);            // buf nb free: reads done before top sync
            LOAD_XH(c + 1, 1);          // LDGs fly under ks 2-3 MMAs
        }

        MMA_STEP(2, sA, sx);
        MMA_STEP(3, sA, sx);

        if (c < 3) STORE_XH(nb, 1);     // next top sync orders before reads
    }

    // ---- Epilogue ----
#pragma unroll
    for (int mt = 0; mt < 4; ++mt) {
        int m = wm * 64 + mt * 16 + gq;
        float b0 = s_bias[m];
        float b1 = s_bias[m + 8];
        int mg = mh * 128 + m;
#pragma unroll
        for (int nt = 0; nt < 4; ++nt) {
            int n = n0 + wn * 32 + nt * 8 + tg * 2;
            float* o0 = out + ((size_t)(b * C_ + mg)) * HW_ + n;
            float2 v0 = make_float2(acc[mt][nt][0] + b0, acc[mt][nt][1] + b0);
            float2 v1 = make_float2(acc[mt][nt][2] + b1, acc[mt][nt][3] + b1);
            *(float2*)o0 = v0;
            *(float2*)(o0 + (size_t)8 * HW_) = v1;
        }
    }
}

// ---------------------------------------------------------------------------
// Launch
// ---------------------------------------------------------------------------
extern "C" void kernel_launch(void* const* d_in, const int* in_sizes, int n_in,
                              void* d_out, int out_size) {
    const float* x      = (const float*)d_in[0];
    const float* params = (const float*)d_in[1];
    const float* W      = (const float*)d_in[2];
    float* out = (float*)d_out;

    cudaFuncSetAttribute(gemm_tc, cudaFuncAttributeMaxDynamicSharedMemorySize,
                         SMEM_BYTES);

    stats_k<<<B_ * C_, 256>>>(x);
    finalize_k<<<B_, 256>>>();
    prep_k<<<B_ * C_, 256>>>(W, params);
    dim3 grid((HW_ / 128) * 2, B_);
    gemm_tc<<<grid, 256, SMEM_BYTES>>>(x, out);
}